// round 2
// baseline (speedup 1.0000x reference)
#include <cuda_runtime.h>
#include <cstdint>
#include <cstddef>

#define NPIX 32768   // B*H*W = 8*64*64
#define CDIM 512
#define KN   1024
#define VC   512
#define HW   4096    // H*W

// ---------------- scratch (static device globals; no allocation) ----------------
__device__ float g_xn[(size_t)NPIX * CDIM];    // normalized x rows (N,C)
__device__ float g_xnorm[NPIX];                // clipped norms
__device__ float g_mn [KN * CDIM];             // normalized noise_feature
__device__ float g_mn2[KN * CDIM];             // normalized updated codebook
__device__ float g_esum[KN * CDIM];            // segment sums
__device__ float g_cnt [KN];                   // segment counts
__device__ int   g_ind [NPIX];                 // argmax indices
__device__ float g_prob[(size_t)NPIX * KN];    // softmax probs (and score2 fallback)

// ---------------- normalize codebook rows ----------------
__global__ __launch_bounds__(128) void k_norm_m(const float* __restrict__ m,
                                                float* __restrict__ dst) {
    int k = blockIdx.x, tid = threadIdx.x;  // 128 threads, 4 floats each
    float4 v = ((const float4*)(m + (size_t)k * CDIM))[tid];
    float ss = v.x*v.x + v.y*v.y + v.z*v.z + v.w*v.w;
    #pragma unroll
    for (int o = 16; o; o >>= 1) ss += __shfl_xor_sync(~0u, ss, o);
    __shared__ float sred[4];
    __shared__ float sinv;
    if ((tid & 31) == 0) sred[tid >> 5] = ss;
    __syncthreads();
    if (tid == 0) {
        float t = sred[0] + sred[1] + sred[2] + sred[3];
        sinv = 1.f / fmaxf(sqrtf(t), 1e-12f);
    }
    __syncthreads();
    float inv = sinv;
    float4 o4 = {v.x*inv, v.y*inv, v.z*inv, v.w*inv};
    ((float4*)(dst + (size_t)k * CDIM))[tid] = o4;
}

// ---------------- EMA update + normalize -> g_mn2 ----------------
__global__ __launch_bounds__(128) void k_update_m(const float* __restrict__ m) {
    int k = blockIdx.x, tid = threadIdx.x;
    float w = 0.001f / (g_cnt[k] + 1e-6f);          // (1-RATE)/ (cnt+1e-6)
    float4 mv = ((const float4*)(m      + (size_t)k * CDIM))[tid];
    float4 ev = ((const float4*)(g_esum + (size_t)k * CDIM))[tid];
    float4 nv = { mv.x*0.999f + ev.x*w, mv.y*0.999f + ev.y*w,
                  mv.z*0.999f + ev.z*w, mv.w*0.999f + ev.w*w };
    float ss = nv.x*nv.x + nv.y*nv.y + nv.z*nv.z + nv.w*nv.w;
    #pragma unroll
    for (int o = 16; o; o >>= 1) ss += __shfl_xor_sync(~0u, ss, o);
    __shared__ float sred[4];
    __shared__ float sinv;
    if ((tid & 31) == 0) sred[tid >> 5] = ss;
    __syncthreads();
    if (tid == 0) {
        float t = sred[0] + sred[1] + sred[2] + sred[3];
        sinv = 1.f / fmaxf(sqrtf(t), 1e-12f);
    }
    __syncthreads();
    float inv = sinv;
    float4 o4 = {nv.x*inv, nv.y*inv, nv.z*inv, nv.w*inv};
    ((float4*)(g_mn2 + (size_t)k * CDIM))[tid] = o4;
}

// ---------------- transpose (b,c,h,w)->(n,c), normalize rows ----------------
// block = 256 threads (16 px × 16 c-lanes); 16 pixels per block
// 2048 blocks total = B(8) * HW/16(256)
__global__ __launch_bounds__(256) void k_prep_x(const float* __restrict__ x) {
    __shared__ float s[CDIM][17];     // [c][px], padded  (~35 KB)
    __shared__ float rsum[16][17];
    int bid = blockIdx.x;             // 0..2047
    int b   = bid >> 8;               // / 256   (FIX: was >>7)
    int hw0 = (bid & 255) << 4;       // * 16    (FIX: was &127)
    int tx = threadIdx.x & 15, ty = threadIdx.x >> 4;
    const float* xb = x + (size_t)b * CDIM * HW + hw0;
    float ss = 0.f;
    for (int c = ty; c < CDIM; c += 16) {
        float v = xb[(size_t)c * HW + tx];
        s[c][tx] = v;
        ss += v * v;
    }
    rsum[ty][tx] = ss;
    __syncthreads();
    if (ty < 8) rsum[ty][tx] += rsum[ty + 8][tx];
    __syncthreads();
    if (ty < 4) rsum[ty][tx] += rsum[ty + 4][tx];
    __syncthreads();
    if (ty < 2) rsum[ty][tx] += rsum[ty + 2][tx];
    __syncthreads();
    if (ty == 0) {
        float tot  = rsum[0][tx] + rsum[1][tx];
        float norm = fmaxf(sqrtf(tot), 1e-12f);
        g_xnorm[b * HW + hw0 + tx] = norm;
        rsum[0][tx] = 1.f / norm;
    }
    __syncthreads();
    int warp = threadIdx.x >> 5, lane = threadIdx.x & 31;
    #pragma unroll
    for (int q = 0; q < 2; q++) {
        int p = warp * 2 + q;
        float inv = rsum[0][p];
        float* dst = g_xn + (size_t)(b * HW + hw0 + p) * CDIM;
        for (int c = lane; c < CDIM; c += 32)
            dst[c] = s[c][p] * inv;
    }
}

// ---------------- zero segment buffers ----------------
__global__ void k_zero() {
    int i = blockIdx.x * blockDim.x + threadIdx.x;
    if (i < KN * CDIM) g_esum[i] = 0.f;
    if (i < KN)        g_cnt[i]  = 0.f;
}

// ---------------- score GEMM: A(N,C) @ B(K,C)^T ; mode0 = argmax, mode1 = store ----
__global__ __launch_bounds__(256) void k_gemm_nt(
    const float* __restrict__ A, const float* __restrict__ Bm,
    float* __restrict__ outp, int mode) {
    __shared__ __align__(16) float As[8][132];
    __shared__ __align__(16) float Bs[8][132];
    int row0 = blockIdx.x * 128;
    int tid = threadIdx.x;
    int tx = tid & 15, ty = tid >> 4;
    int lr = tid >> 1;
    int lc = (tid & 1) * 4;
    float bestv[8]; int besti[8];
    #pragma unroll
    for (int i = 0; i < 8; i++) { bestv[i] = -3.4e38f; besti[i] = 0; }

    for (int kk = 0; kk < KN; kk += 128) {
        float acc[64];
        #pragma unroll
        for (int i = 0; i < 64; i++) acc[i] = 0.f;
        for (int ct = 0; ct < CDIM; ct += 8) {
            float4 av = *(const float4*)(A  + (size_t)(row0 + lr) * CDIM + ct + lc);
            float4 bv = *(const float4*)(Bm + (size_t)(kk   + lr) * CDIM + ct + lc);
            __syncthreads();
            As[lc][lr] = av.x; As[lc+1][lr] = av.y; As[lc+2][lr] = av.z; As[lc+3][lr] = av.w;
            Bs[lc][lr] = bv.x; Bs[lc+1][lr] = bv.y; Bs[lc+2][lr] = bv.z; Bs[lc+3][lr] = bv.w;
            __syncthreads();
            #pragma unroll
            for (int cc = 0; cc < 8; cc++) {
                float a[8], b[8];
                *(float4*)(a)     = *(const float4*)&As[cc][ty * 8];
                *(float4*)(a + 4) = *(const float4*)&As[cc][ty * 8 + 4];
                *(float4*)(b)     = *(const float4*)&Bs[cc][tx * 8];
                *(float4*)(b + 4) = *(const float4*)&Bs[cc][tx * 8 + 4];
                #pragma unroll
                for (int i = 0; i < 8; i++)
                    #pragma unroll
                    for (int j = 0; j < 8; j++)
                        acc[i * 8 + j] = fmaf(a[i], b[j], acc[i * 8 + j]);
            }
        }
        if (mode == 0) {
            #pragma unroll
            for (int i = 0; i < 8; i++) {
                float v = acc[i * 8]; int jj = 0;
                #pragma unroll
                for (int j = 1; j < 8; j++)
                    if (acc[i * 8 + j] > v) { v = acc[i * 8 + j]; jj = j; }
                int idx = kk + tx * 8 + jj;
                #pragma unroll
                for (int off = 8; off > 0; off >>= 1) {
                    float ov = __shfl_down_sync(~0u, v,   off, 16);
                    int   oi = __shfl_down_sync(~0u, idx, off, 16);
                    if (ov > v) { v = ov; idx = oi; }   // strict > keeps lowest idx
                }
                if (tx == 0 && v > bestv[i]) { bestv[i] = v; besti[i] = idx; }
            }
        } else {
            #pragma unroll
            for (int i = 0; i < 8; i++) {
                float* o = outp + (size_t)(row0 + ty * 8 + i) * KN + kk + tx * 8;
                *(float4*)o       = *(const float4*)&acc[i * 8];
                *(float4*)(o + 4) = *(const float4*)&acc[i * 8 + 4];
            }
        }
    }
    if (mode == 0 && tx == 0) {
        #pragma unroll
        for (int i = 0; i < 8; i++) g_ind[row0 + ty * 8 + i] = besti[i];
    }
}

// ---------------- segment counts / sums (atomics) ----------------
__global__ void k_counts() {
    int n = blockIdx.x * blockDim.x + threadIdx.x;
    if (n < NPIX) atomicAdd(&g_cnt[g_ind[n]], 1.f);
}

__global__ void k_scatter() {
    int i = blockIdx.x * blockDim.x + threadIdx.x;   // N*C threads
    int n = i >> 9, c = i & 511;
    float v = g_xn[(size_t)i] * g_xnorm[n];          // recover xf
    atomicAdd(&g_esum[(size_t)g_ind[n] * CDIM + c], v);
}

// ---------------- softmax rows of score2 ----------------
__global__ __launch_bounds__(256) void k_softmax(const float* __restrict__ s2,
                                                 float* __restrict__ prob) {
    int n = blockIdx.x, tid = threadIdx.x;
    float4 v = ((const float4*)(s2 + (size_t)n * KN))[tid];
    float mx = fmaxf(fmaxf(v.x, v.y), fmaxf(v.z, v.w));
    #pragma unroll
    for (int o = 16; o; o >>= 1) mx = fmaxf(mx, __shfl_xor_sync(~0u, mx, o));
    __shared__ float sm[8];
    if ((tid & 31) == 0) sm[tid >> 5] = mx;
    __syncthreads();
    if (tid < 32) {
        float t = (tid < 8) ? sm[tid] : -3.4e38f;
        #pragma unroll
        for (int o = 4; o; o >>= 1) t = fmaxf(t, __shfl_xor_sync(~0u, t, o));
        if (tid == 0) sm[0] = t;
    }
    __syncthreads();
    float M = sm[0];
    float e0 = __expf(v.x - M), e1 = __expf(v.y - M);
    float e2 = __expf(v.z - M), e3 = __expf(v.w - M);
    float s = e0 + e1 + e2 + e3;
    #pragma unroll
    for (int o = 16; o; o >>= 1) s += __shfl_xor_sync(~0u, s, o);
    __shared__ float ssum[8];
    if ((tid & 31) == 0) ssum[tid >> 5] = s;
    __syncthreads();
    if (tid < 32) {
        float t = (tid < 8) ? ssum[tid] : 0.f;
        #pragma unroll
        for (int o = 4; o; o >>= 1) t += __shfl_xor_sync(~0u, t, o);
        if (tid == 0) ssum[0] = t;
    }
    __syncthreads();
    float inv = 1.f / ssum[0];
    float4 o4 = {e0 * inv, e1 * inv, e2 * inv, e3 * inv};
    ((float4*)(prob + (size_t)n * KN))[tid] = o4;
}

// ---------------- out = P(N,K) @ std(K,V) ----------------
__global__ __launch_bounds__(256) void k_gemm_nn(
    const float* __restrict__ A, const float* __restrict__ B,
    float* __restrict__ outp) {
    __shared__ __align__(16) float As[8][132];
    __shared__ __align__(16) float Bs[8][132];
    int row0 = blockIdx.x * 128;
    int col0 = blockIdx.y * 128;
    int tid = threadIdx.x;
    int tx = tid & 15, ty = tid >> 4;
    int lr = tid >> 1, lc = (tid & 1) * 4;
    int br = tid >> 5, bc = (tid & 31) * 4;
    float acc[64];
    #pragma unroll
    for (int i = 0; i < 64; i++) acc[i] = 0.f;
    for (int kt = 0; kt < KN; kt += 8) {
        float4 av = *(const float4*)(A + (size_t)(row0 + lr) * KN + kt + lc);
        float4 bv = *(const float4*)(B + (size_t)(kt + br) * VC + col0 + bc);
        __syncthreads();
        As[lc][lr] = av.x; As[lc+1][lr] = av.y; As[lc+2][lr] = av.z; As[lc+3][lr] = av.w;
        *(float4*)&Bs[br][bc] = bv;
        __syncthreads();
        #pragma unroll
        for (int cc = 0; cc < 8; cc++) {
            float a[8], b[8];
            *(float4*)(a)     = *(const float4*)&As[cc][ty * 8];
            *(float4*)(a + 4) = *(const float4*)&As[cc][ty * 8 + 4];
            *(float4*)(b)     = *(const float4*)&Bs[cc][tx * 8];
            *(float4*)(b + 4) = *(const float4*)&Bs[cc][tx * 8 + 4];
            #pragma unroll
            for (int i = 0; i < 8; i++)
                #pragma unroll
                for (int j = 0; j < 8; j++)
                    acc[i * 8 + j] = fmaf(a[i], b[j], acc[i * 8 + j]);
        }
    }
    #pragma unroll
    for (int i = 0; i < 8; i++) {
        float* o = outp + (size_t)(row0 + ty * 8 + i) * VC + col0 + tx * 8;
        *(float4*)o       = *(const float4*)&acc[i * 8];
        *(float4*)(o + 4) = *(const float4*)&acc[i * 8 + 4];
    }
}

// ---------------- launch ----------------
extern "C" void kernel_launch(void* const* d_in, const int* in_sizes, int n_in,
                              void* d_out, int out_size) {
    const float* x    = (const float*)d_in[0];   // (8,512,64,64)
    const float* m    = (const float*)d_in[1];   // (1024,512)
    const float* stdw = (const float*)d_in[2];   // (1024,512)
    float* out = (float*)d_out;

    float *p_xn, *p_mn, *p_mn2, *p_prob;
    cudaGetSymbolAddress((void**)&p_xn,   g_xn);
    cudaGetSymbolAddress((void**)&p_mn,   g_mn);
    cudaGetSymbolAddress((void**)&p_mn2,  g_mn2);
    cudaGetSymbolAddress((void**)&p_prob, g_prob);

    const long long OUT1 = (long long)NPIX * VC;            // 16,777,216
    const long long S2SZ = (long long)NPIX * KN;            // 33,554,432
    // If d_out also holds score2 (tuple output), write it there; else fallback scratch.
    float* s2 = ((long long)out_size >= OUT1 + S2SZ) ? (out + OUT1) : p_prob;

    k_norm_m <<<KN, 128>>>(m, p_mn);
    k_prep_x <<<2048, 256>>>(x);
    k_zero   <<<(KN * CDIM + 255) / 256, 256>>>();
    k_gemm_nt<<<NPIX / 128, 256>>>(p_xn, p_mn, nullptr, 0);      // score1 + argmax
    k_counts <<<NPIX / 256, 256>>>();
    k_scatter<<<(NPIX * CDIM) / 256, 256>>>();
    k_update_m<<<KN, 128>>>(m);
    k_gemm_nt<<<NPIX / 128, 256>>>(p_xn, p_mn2, s2, 1);          // score2
    k_softmax<<<NPIX, 256>>>(s2, p_prob);
    k_gemm_nn<<<dim3(NPIX / 128, VC / 128), 256>>>(p_prob, stdw, out);
}

// round 4
// speedup vs baseline: 2.7064x; 2.7064x over previous
#include <cuda_runtime.h>
#include <cuda_bf16.h>
#include <cstdint>
#include <cstddef>

#define NPIX 32768   // B*H*W = 8*64*64
#define CDIM 512
#define KN   1024
#define VC   512
#define HW   4096    // H*W

typedef unsigned long long u64;

// ---------------- scratch (static device globals; no allocation) ----------------
__device__ float g_xn[(size_t)NPIX * CDIM];          // normalized x rows (N,C) fp32
__device__ float g_xnorm[NPIX];                      // clipped norms
__device__ __nv_bfloat16 g_xh[(size_t)NPIX * CDIM];  // xn hi
__device__ __nv_bfloat16 g_xl[(size_t)NPIX * CDIM];  // xn lo
__device__ __nv_bfloat16 g_mh [KN * CDIM], g_ml [KN * CDIM];
__device__ __nv_bfloat16 g_m2h[KN * CDIM], g_m2l[KN * CDIM];
__device__ __nv_bfloat16 g_sth[(size_t)VC * KN], g_stl[(size_t)VC * KN]; // std^T hi/lo
__device__ __nv_bfloat16 g_ph[(size_t)NPIX * KN], g_pl[(size_t)NPIX * KN]; // prob hi/lo
__device__ float g_esum[KN * CDIM];
__device__ float g_cnt [KN];
__device__ int   g_ind [NPIX];
__device__ u64   g_arg [NPIX];                       // encoded (score,~idx) argmax
__device__ float g_prob[(size_t)NPIX * KN];          // fp32 score2 fallback buffer

// ============================= PTX helpers (portable, sm_80+) =============================
__device__ __forceinline__ uint32_t smem_u32(const void* p) {
    uint32_t a;
    asm("{ .reg .u64 t; cvta.to.shared.u64 t, %1; cvt.u32.u64 %0, t; }" : "=r"(a) : "l"(p));
    return a;
}
__device__ __forceinline__ void cp16(uint32_t saddr, const void* gaddr) {
    asm volatile("cp.async.cg.shared.global [%0], [%1], 16;" :: "r"(saddr), "l"(gaddr));
}
__device__ __forceinline__ void cp_commit() {
    asm volatile("cp.async.commit_group;" ::: "memory");
}
template <int N>
__device__ __forceinline__ void cp_wait() {
    asm volatile("cp.async.wait_group %0;" :: "n"(N) : "memory");
}
__device__ __forceinline__ void ldsm4(uint32_t* r, uint32_t addr) {
    asm volatile("ldmatrix.sync.aligned.m8n8.x4.shared.b16 {%0,%1,%2,%3}, [%4];"
                 : "=r"(r[0]), "=r"(r[1]), "=r"(r[2]), "=r"(r[3]) : "r"(addr));
}
__device__ __forceinline__ void mma16816(float* d, const uint32_t* a, uint32_t b0, uint32_t b1) {
    asm volatile("mma.sync.aligned.m16n8k16.row.col.f32.bf16.bf16.f32 "
                 "{%0,%1,%2,%3}, {%4,%5,%6,%7}, {%8,%9}, {%0,%1,%2,%3};"
                 : "+f"(d[0]), "+f"(d[1]), "+f"(d[2]), "+f"(d[3])
                 : "r"(a[0]), "r"(a[1]), "r"(a[2]), "r"(a[3]), "r"(b0), "r"(b1));
}
__device__ __forceinline__ unsigned fenc(float f) {
    unsigned u = __float_as_uint(f);
    return (u & 0x80000000u) ? ~u : (u | 0x80000000u);
}

// SMEM: 2 buffers x {AH,AL,BH,BL}, each tile 128 rows x 80B (32 bf16 data + pad)
#define ROWB 80
#define TILEB (128 * ROWB)          // 10240
#define SMEM_DYN (8 * TILEB)        // 81920

// ============ HMMA GEMM: C(M,Nc tile 128x128) = A(M,Cd) @ B(Nc,Cd)^T, bf16 hi/lo ============
// mode 0: argmax over row -> g_arg (hi-only pass); mode 1/2: store fp32 to outp (width outW)
__global__ void __launch_bounds__(256, 1) k_mma(
    const __nv_bfloat16* __restrict__ Ah, const __nv_bfloat16* __restrict__ Al,
    const __nv_bfloat16* __restrict__ Bh, const __nv_bfloat16* __restrict__ Bl,
    int Cd, int outW, int mode, float* __restrict__ outp)
{
    extern __shared__ char smc[];
    const int tid = threadIdx.x, warp = tid >> 5, lane = tid & 31;
    const int wm = warp >> 2, wn = warp & 3;     // 2 x 4 warp grid, warp tile 64x32
    const int row0 = blockIdx.x * 128, col0 = blockIdx.y * 128;
    const bool hiOnly = (mode == 0);

    const uint32_t sAH = smem_u32(smc);
    const uint32_t sAL = sAH + 2 * TILEB;
    const uint32_t sBH = sAH + 4 * TILEB;
    const uint32_t sBL = sAH + 6 * TILEB;

    const int nCh = Cd >> 5;   // chunks of 32 bf16 cols

    auto loadTile = [&](const __nv_bfloat16* G, uint32_t sbase, int gr0, int c0) {
        #pragma unroll
        for (int q = 0; q < 2; q++) {
            int u = tid + q * 256;           // 512 16B units
            int r = u >> 2, uo = u & 3;
            cp16(sbase + r * ROWB + uo * 16, G + (size_t)(gr0 + r) * Cd + c0 + uo * 8);
        }
    };
    auto loadChunk = [&](int c, int buf) {
        int c0 = c << 5;
        loadTile(Ah, sAH + buf * TILEB, row0, c0);
        loadTile(Bh, sBH + buf * TILEB, col0, c0);
        if (!hiOnly) {
            loadTile(Al, sAL + buf * TILEB, row0, c0);
            loadTile(Bl, sBL + buf * TILEB, col0, c0);
        }
        cp_commit();
    };

    float acc[4][4][4];
    #pragma unroll
    for (int i = 0; i < 4; i++)
        #pragma unroll
        for (int j = 0; j < 4; j++)
            #pragma unroll
            for (int q = 0; q < 4; q++) acc[i][j][q] = 0.f;

    loadChunk(0, 0);
    for (int c = 0; c < nCh; c++) {
        int buf = c & 1;
        if (c + 1 < nCh) { loadChunk(c + 1, (c + 1) & 1); cp_wait<1>(); }
        else             { cp_wait<0>(); }
        __syncthreads();

        uint32_t aH = sAH + buf * TILEB, aL = sAL + buf * TILEB;
        uint32_t bH = sBH + buf * TILEB, bL = sBL + buf * TILEB;
        #pragma unroll
        for (int s = 0; s < 2; s++) {
            uint32_t ah[4][4], al[4][4], bh[2][4], bl[2][4];
            #pragma unroll
            for (int mt = 0; mt < 4; mt++) {
                uint32_t off = (uint32_t)(wm * 64 + mt * 16 + (lane & 15)) * ROWB
                             + (lane >> 4) * 16 + s * 32;
                ldsm4(ah[mt], aH + off);
                if (!hiOnly) ldsm4(al[mt], aL + off);
            }
            #pragma unroll
            for (int np = 0; np < 2; np++) {
                uint32_t off = (uint32_t)(wn * 32 + np * 16 + (lane & 15)) * ROWB
                             + (lane >> 4) * 16 + s * 32;
                ldsm4(bh[np], bH + off);
                if (!hiOnly) ldsm4(bl[np], bL + off);
            }
            #pragma unroll
            for (int mt = 0; mt < 4; mt++)
                #pragma unroll
                for (int nt = 0; nt < 4; nt++) {
                    int np = nt >> 1, half = nt & 1;
                    mma16816(acc[mt][nt], ah[mt], bh[np][half], bh[np][half + 2]);
                    if (!hiOnly) {
                        mma16816(acc[mt][nt], ah[mt], bl[np][half], bl[np][half + 2]);
                        mma16816(acc[mt][nt], al[mt], bh[np][half], bh[np][half + 2]);
                    }
                }
        }
        __syncthreads();
    }

    // ----------------- epilogue -----------------
    if (mode == 0) {
        #pragma unroll
        for (int mt = 0; mt < 4; mt++) {
            int rg = row0 + wm * 64 + mt * 16 + (lane >> 2);
            u64 bA = 0, bB = 0;
            #pragma unroll
            for (int nt = 0; nt < 4; nt++) {
                unsigned cb = (unsigned)(col0 + wn * 32 + nt * 8 + (lane & 3) * 2);
                u64 e;
                e = ((u64)fenc(acc[mt][nt][0]) << 32) | (unsigned)(~cb);       if (e > bA) bA = e;
                e = ((u64)fenc(acc[mt][nt][1]) << 32) | (unsigned)(~(cb + 1)); if (e > bA) bA = e;
                e = ((u64)fenc(acc[mt][nt][2]) << 32) | (unsigned)(~cb);       if (e > bB) bB = e;
                e = ((u64)fenc(acc[mt][nt][3]) << 32) | (unsigned)(~(cb + 1)); if (e > bB) bB = e;
            }
            #pragma unroll
            for (int off = 1; off <= 2; off <<= 1) {
                u64 oA = __shfl_xor_sync(~0u, bA, off);
                u64 oB = __shfl_xor_sync(~0u, bB, off);
                if (oA > bA) bA = oA;
                if (oB > bB) bB = oB;
            }
            if ((lane & 3) == 0) {
                atomicMax(&g_arg[rg], bA);
                atomicMax(&g_arg[rg + 8], bB);
            }
        }
    } else {
        #pragma unroll
        for (int mt = 0; mt < 4; mt++) {
            int rg = row0 + wm * 64 + mt * 16 + (lane >> 2);
            #pragma unroll
            for (int nt = 0; nt < 4; nt++) {
                int cg = col0 + wn * 32 + nt * 8 + (lane & 3) * 2;
                float2 lo = {acc[mt][nt][0], acc[mt][nt][1]};
                float2 hi = {acc[mt][nt][2], acc[mt][nt][3]};
                *(float2*)(outp + (size_t)rg * outW + cg)       = lo;
                *(float2*)(outp + (size_t)(rg + 8) * outW + cg) = hi;
            }
        }
    }
}

// ---------------- normalize codebook rows -> bf16 hi/lo ----------------
__global__ __launch_bounds__(128) void k_norm_m(const float* __restrict__ m,
                                                __nv_bfloat16* __restrict__ dh,
                                                __nv_bfloat16* __restrict__ dl) {
    int k = blockIdx.x, tid = threadIdx.x;
    float4 v = ((const float4*)(m + (size_t)k * CDIM))[tid];
    float ss = v.x*v.x + v.y*v.y + v.z*v.z + v.w*v.w;
    #pragma unroll
    for (int o = 16; o; o >>= 1) ss += __shfl_xor_sync(~0u, ss, o);
    __shared__ float sred[4]; __shared__ float sinv;
    if ((tid & 31) == 0) sred[tid >> 5] = ss;
    __syncthreads();
    if (tid == 0) sinv = 1.f / fmaxf(sqrtf(sred[0]+sred[1]+sred[2]+sred[3]), 1e-12f);
    __syncthreads();
    float inv = sinv;
    float o4[4] = {v.x*inv, v.y*inv, v.z*inv, v.w*inv};
    size_t base = (size_t)k * CDIM + tid * 4;
    #pragma unroll
    for (int j = 0; j < 4; j++) {
        __nv_bfloat16 h = __float2bfloat16(o4[j]);
        dh[base + j] = h;
        dl[base + j] = __float2bfloat16(o4[j] - __bfloat162float(h));
    }
}

// ---------------- EMA update + normalize -> bf16 hi/lo ----------------
__global__ __launch_bounds__(128) void k_update_m(const float* __restrict__ m) {
    int k = blockIdx.x, tid = threadIdx.x;
    float w = 0.001f / (g_cnt[k] + 1e-6f);
    float4 mv = ((const float4*)(m      + (size_t)k * CDIM))[tid];
    float4 ev = ((const float4*)(g_esum + (size_t)k * CDIM))[tid];
    float nv[4] = { mv.x*0.999f + ev.x*w, mv.y*0.999f + ev.y*w,
                    mv.z*0.999f + ev.z*w, mv.w*0.999f + ev.w*w };
    float ss = nv[0]*nv[0] + nv[1]*nv[1] + nv[2]*nv[2] + nv[3]*nv[3];
    #pragma unroll
    for (int o = 16; o; o >>= 1) ss += __shfl_xor_sync(~0u, ss, o);
    __shared__ float sred[4]; __shared__ float sinv;
    if ((tid & 31) == 0) sred[tid >> 5] = ss;
    __syncthreads();
    if (tid == 0) sinv = 1.f / fmaxf(sqrtf(sred[0]+sred[1]+sred[2]+sred[3]), 1e-12f);
    __syncthreads();
    float inv = sinv;
    size_t base = (size_t)k * CDIM + tid * 4;
    #pragma unroll
    for (int j = 0; j < 4; j++) {
        float v = nv[j] * inv;
        __nv_bfloat16 h = __float2bfloat16(v);
        g_m2h[base + j] = h;
        g_m2l[base + j] = __float2bfloat16(v - __bfloat162float(h));
    }
}

// ---------------- transpose std (K,V)->(V,K), bf16 hi/lo ----------------
__global__ void k_tstd(const float* __restrict__ s) {
    __shared__ float t[32][33];
    int v0 = blockIdx.x * 32, k0 = blockIdx.y * 32;
    int tx = threadIdx.x, ty = threadIdx.y;  // 32 x 8
    #pragma unroll
    for (int i = 0; i < 4; i++)
        t[ty + 8*i][tx] = s[(size_t)(k0 + ty + 8*i) * VC + v0 + tx];
    __syncthreads();
    #pragma unroll
    for (int i = 0; i < 4; i++) {
        float v = t[tx][ty + 8*i];
        __nv_bfloat16 h = __float2bfloat16(v);
        size_t o = (size_t)(v0 + ty + 8*i) * KN + k0 + tx;
        g_sth[o] = h;
        g_stl[o] = __float2bfloat16(v - __bfloat162float(h));
    }
}

// ---------------- transpose (b,c,h,w)->(n,c), normalize rows ----------------
__global__ __launch_bounds__(256) void k_prep_x(const float* __restrict__ x) {
    __shared__ float s[CDIM][17];
    __shared__ float rsum[16][17];
    int bid = blockIdx.x;             // 0..2047
    int b   = bid >> 8;               // / 256
    int hw0 = (bid & 255) << 4;       // * 16
    int tx = threadIdx.x & 15, ty = threadIdx.x >> 4;
    const float* xb = x + (size_t)b * CDIM * HW + hw0;
    float ss = 0.f;
    for (int c = ty; c < CDIM; c += 16) {
        float v = xb[(size_t)c * HW + tx];
        s[c][tx] = v;
        ss += v * v;
    }
    rsum[ty][tx] = ss;
    __syncthreads();
    if (ty < 8) rsum[ty][tx] += rsum[ty + 8][tx];
    __syncthreads();
    if (ty < 4) rsum[ty][tx] += rsum[ty + 4][tx];
    __syncthreads();
    if (ty < 2) rsum[ty][tx] += rsum[ty + 2][tx];
    __syncthreads();
    if (ty == 0) {
        float norm = fmaxf(sqrtf(rsum[0][tx] + rsum[1][tx]), 1e-12f);
        g_xnorm[b * HW + hw0 + tx] = norm;
        rsum[0][tx] = 1.f / norm;
    }
    __syncthreads();
    int warp = threadIdx.x >> 5, lane = threadIdx.x & 31;
    #pragma unroll
    for (int q = 0; q < 2; q++) {
        int p = warp * 2 + q;
        float inv = rsum[0][p];
        size_t rbase = (size_t)(b * HW + hw0 + p) * CDIM;
        for (int c = lane; c < CDIM; c += 32) {
            float v = s[c][p] * inv;
            g_xn[rbase + c] = v;
            __nv_bfloat16 h = __float2bfloat16(v);
            g_xh[rbase + c] = h;
            g_xl[rbase + c] = __float2bfloat16(v - __bfloat162float(h));
        }
    }
}

// ---------------- zero segment buffers + argmax buffer ----------------
__global__ void k_zero() {
    int i = blockIdx.x * blockDim.x + threadIdx.x;
    if (i < KN * CDIM) g_esum[i] = 0.f;
    if (i < KN)        g_cnt[i]  = 0.f;
    if (i < NPIX)      g_arg[i]  = 0ull;
}

// ---------------- counts (decodes argmax) / scatter ----------------
__global__ void k_counts() {
    int n = blockIdx.x * blockDim.x + threadIdx.x;
    if (n < NPIX) {
        int idx = (int)(~(unsigned)(g_arg[n] & 0xFFFFFFFFull));
        g_ind[n] = idx;
        atomicAdd(&g_cnt[idx], 1.f);
    }
}
__global__ void k_scatter() {
    int i = blockIdx.x * blockDim.x + threadIdx.x;
    int n = i >> 9, c = i & 511;
    float v = g_xn[(size_t)i] * g_xnorm[n];
    atomicAdd(&g_esum[(size_t)g_ind[n] * CDIM + c], v);
}

// ---------------- softmax rows of score2 -> bf16 hi/lo prob ----------------
__global__ __launch_bounds__(256) void k_softmax(const float* __restrict__ s2) {
    int n = blockIdx.x, tid = threadIdx.x;
    float4 v = ((const float4*)(s2 + (size_t)n * KN))[tid];
    float mx = fmaxf(fmaxf(v.x, v.y), fmaxf(v.z, v.w));
    #pragma unroll
    for (int o = 16; o; o >>= 1) mx = fmaxf(mx, __shfl_xor_sync(~0u, mx, o));
    __shared__ float sm[8];
    if ((tid & 31) == 0) sm[tid >> 5] = mx;
    __syncthreads();
    if (tid < 32) {
        float t = (tid < 8) ? sm[tid] : -3.4e38f;
        #pragma unroll
        for (int o = 4; o; o >>= 1) t = fmaxf(t, __shfl_xor_sync(~0u, t, o));
        if (tid == 0) sm[0] = t;
    }
    __syncthreads();
    float M = sm[0];
    float e0 = __expf(v.x - M), e1 = __expf(v.y - M);
    float e2 = __expf(v.z - M), e3 = __expf(v.w - M);
    float ssum = e0 + e1 + e2 + e3;
    #pragma unroll
    for (int o = 16; o; o >>= 1) ssum += __shfl_xor_sync(~0u, ssum, o);
    __shared__ float sq[8];
    if ((tid & 31) == 0) sq[tid >> 5] = ssum;
    __syncthreads();
    if (tid < 32) {
        float t = (tid < 8) ? sq[tid] : 0.f;
        #pragma unroll
        for (int o = 4; o; o >>= 1) t += __shfl_xor_sync(~0u, t, o);
        if (tid == 0) sq[0] = t;
    }
    __syncthreads();
    float inv = 1.f / sq[0];
    float p[4] = {e0 * inv, e1 * inv, e2 * inv, e3 * inv};
    size_t base = (size_t)n * KN + tid * 4;
    #pragma unroll
    for (int j = 0; j < 4; j++) {
        __nv_bfloat16 h = __float2bfloat16(p[j]);
        g_ph[base + j] = h;
        g_pl[base + j] = __float2bfloat16(p[j] - __bfloat162float(h));
    }
}

// ---------------- launch ----------------
extern "C" void kernel_launch(void* const* d_in, const int* in_sizes, int n_in,
                              void* d_out, int out_size) {
    const float* x    = (const float*)d_in[0];   // (8,512,64,64)
    const float* m    = (const float*)d_in[1];   // (1024,512)
    const float* stdw = (const float*)d_in[2];   // (1024,512)
    float* out = (float*)d_out;

    __nv_bfloat16 *p_xh, *p_xl, *p_mh, *p_ml, *p_m2h, *p_m2l, *p_sth, *p_stl, *p_ph, *p_pl;
    float* p_prob;
    cudaGetSymbolAddress((void**)&p_xh,  g_xh);
    cudaGetSymbolAddress((void**)&p_xl,  g_xl);
    cudaGetSymbolAddress((void**)&p_mh,  g_mh);
    cudaGetSymbolAddress((void**)&p_ml,  g_ml);
    cudaGetSymbolAddress((void**)&p_m2h, g_m2h);
    cudaGetSymbolAddress((void**)&p_m2l, g_m2l);
    cudaGetSymbolAddress((void**)&p_sth, g_sth);
    cudaGetSymbolAddress((void**)&p_stl, g_stl);
    cudaGetSymbolAddress((void**)&p_ph,  g_ph);
    cudaGetSymbolAddress((void**)&p_pl,  g_pl);
    cudaGetSymbolAddress((void**)&p_prob, g_prob);

    cudaFuncSetAttribute(k_mma, cudaFuncAttributeMaxDynamicSharedMemorySize, SMEM_DYN);

    const long long OUT1 = (long long)NPIX * VC;
    const long long S2SZ = (long long)NPIX * KN;
    float* s2 = ((long long)out_size >= OUT1 + S2SZ) ? (out + OUT1) : p_prob;

    k_tstd   <<<dim3(VC / 32, KN / 32), dim3(32, 8)>>>(stdw);
    k_norm_m <<<KN, 128>>>(m, p_mh, p_ml);
    k_prep_x <<<2048, 256>>>(x);
    k_zero   <<<(KN * CDIM + 255) / 256, 256>>>();
    // GEMM1: score1 + argmax (hi-only pass)
    k_mma<<<dim3(NPIX / 128, KN / 128), 256, SMEM_DYN>>>(p_xh, p_xl, p_mh, p_ml,
                                                         CDIM, KN, 0, nullptr);
    k_counts <<<NPIX / 256, 256>>>();
    k_scatter<<<(NPIX * CDIM) / 256, 256>>>();
    k_update_m<<<KN, 128>>>(m);
    // GEMM2: score2 (3-pass hi/lo)
    k_mma<<<dim3(NPIX / 128, KN / 128), 256, SMEM_DYN>>>(p_xh, p_xl, p_m2h, p_m2l,
                                                         CDIM, KN, 1, s2);
    k_softmax<<<NPIX, 256>>>(s2);
    // GEMM3: out = prob @ std (3-pass hi/lo, operands prob(N,K), std^T(V,K))
    k_mma<<<dim3(NPIX / 128, VC / 128), 256, SMEM_DYN>>>(p_ph, p_pl, p_sth, p_stl,
                                                         KN, VC, 2, out);
}

// round 5
// speedup vs baseline: 3.0456x; 1.1253x over previous
#include <cuda_runtime.h>
#include <cuda_bf16.h>
#include <cstdint>
#include <cstddef>

#define NPIX 32768   // B*H*W = 8*64*64
#define CDIM 512
#define KN   1024
#define VC   512
#define HW   4096    // H*W

typedef unsigned long long u64;

// ---------------- scratch (static device globals; no allocation) ----------------
__device__ float g_xnorm[NPIX];                      // clipped norms
__device__ __nv_bfloat16 g_xh[(size_t)NPIX * CDIM];  // xn hi
__device__ __nv_bfloat16 g_xl[(size_t)NPIX * CDIM];  // xn lo
__device__ __nv_bfloat16 g_mh [KN * CDIM], g_ml [KN * CDIM];
__device__ __nv_bfloat16 g_m2h[KN * CDIM], g_m2l[KN * CDIM];
__device__ __nv_bfloat16 g_sth[(size_t)VC * KN], g_stl[(size_t)VC * KN]; // std^T hi/lo
__device__ __nv_bfloat16 g_ph[(size_t)NPIX * KN], g_pl[(size_t)NPIX * KN]; // prob hi/lo
__device__ float g_esum[KN * CDIM];
__device__ float g_cnt [KN];
__device__ int   g_ind [NPIX];
__device__ u64   g_arg [NPIX];                       // encoded (score,~idx) argmax
__device__ float g_prob[(size_t)NPIX * KN];          // fp32 score2 fallback buffer

// ============================= PTX helpers (portable, sm_80+) =============================
__device__ __forceinline__ uint32_t smem_u32(const void* p) {
    uint32_t a;
    asm("{ .reg .u64 t; cvta.to.shared.u64 t, %1; cvt.u32.u64 %0, t; }" : "=r"(a) : "l"(p));
    return a;
}
__device__ __forceinline__ void cp16(uint32_t saddr, const void* gaddr) {
    asm volatile("cp.async.cg.shared.global [%0], [%1], 16;" :: "r"(saddr), "l"(gaddr));
}
__device__ __forceinline__ void cp_commit() {
    asm volatile("cp.async.commit_group;" ::: "memory");
}
template <int N>
__device__ __forceinline__ void cp_wait() {
    asm volatile("cp.async.wait_group %0;" :: "n"(N) : "memory");
}
__device__ __forceinline__ void ldsm4(uint32_t* r, uint32_t addr) {
    asm volatile("ldmatrix.sync.aligned.m8n8.x4.shared.b16 {%0,%1,%2,%3}, [%4];"
                 : "=r"(r[0]), "=r"(r[1]), "=r"(r[2]), "=r"(r[3]) : "r"(addr));
}
__device__ __forceinline__ void mma16816(float* d, const uint32_t* a, uint32_t b0, uint32_t b1) {
    asm volatile("mma.sync.aligned.m16n8k16.row.col.f32.bf16.bf16.f32 "
                 "{%0,%1,%2,%3}, {%4,%5,%6,%7}, {%8,%9}, {%0,%1,%2,%3};"
                 : "+f"(d[0]), "+f"(d[1]), "+f"(d[2]), "+f"(d[3])
                 : "r"(a[0]), "r"(a[1]), "r"(a[2]), "r"(a[3]), "r"(b0), "r"(b1));
}
__device__ __forceinline__ unsigned fenc(float f) {
    unsigned u = __float_as_uint(f);
    return (u & 0x80000000u) ? ~u : (u | 0x80000000u);
}

// SMEM: 2 buffers x {AH,AL,BH,BL}; tile = 128 rows x (64 bf16 = 128B + 16B pad)
#define ROWB 144
#define TILEB (128 * ROWB)          // 18432
#define SMEM_DYN (8 * TILEB)        // 147456

// ============ HMMA GEMM: C(M,Nc tile 128x128) = A(M,Cd) @ B(Nc,Cd)^T, bf16 hi/lo ============
// blockIdx.x = COL tile (fast -> consecutive CTAs share the A row tile in L2)
// blockIdx.y = ROW tile
// mode 0: argmax over row -> g_arg (hi-only pass); mode 1/2: store fp32 to outp (width outW)
__global__ void __launch_bounds__(256, 1) k_mma(
    const __nv_bfloat16* __restrict__ Ah, const __nv_bfloat16* __restrict__ Al,
    const __nv_bfloat16* __restrict__ Bh, const __nv_bfloat16* __restrict__ Bl,
    int Cd, int outW, int mode, float* __restrict__ outp)
{
    extern __shared__ char smc[];
    const int tid = threadIdx.x, warp = tid >> 5, lane = tid & 31;
    const int wm = warp >> 2, wn = warp & 3;     // 2 x 4 warp grid, warp tile 64x32
    const int row0 = blockIdx.y * 128, col0 = blockIdx.x * 128;
    const bool hiOnly = (mode == 0);

    const uint32_t sAH = smem_u32(smc);
    const uint32_t sAL = sAH + 2 * TILEB;
    const uint32_t sBH = sAH + 4 * TILEB;
    const uint32_t sBL = sAH + 6 * TILEB;

    const int nCh = Cd >> 6;   // chunks of 64 bf16 cols

    auto loadTile = [&](const __nv_bfloat16* G, uint32_t sbase, int gr0, int c0) {
        #pragma unroll
        for (int q = 0; q < 4; q++) {
            int u = tid + q * 256;           // 1024 16B units (128 rows x 8)
            int r = u >> 3, uo = u & 7;
            cp16(sbase + r * ROWB + uo * 16, G + (size_t)(gr0 + r) * Cd + c0 + uo * 8);
        }
    };
    auto loadChunk = [&](int c, int buf) {
        int c0 = c << 6;
        loadTile(Ah, sAH + buf * TILEB, row0, c0);
        loadTile(Bh, sBH + buf * TILEB, col0, c0);
        if (!hiOnly) {
            loadTile(Al, sAL + buf * TILEB, row0, c0);
            loadTile(Bl, sBL + buf * TILEB, col0, c0);
        }
        cp_commit();
    };

    float acc[4][4][4];
    #pragma unroll
    for (int i = 0; i < 4; i++)
        #pragma unroll
        for (int j = 0; j < 4; j++)
            #pragma unroll
            for (int q = 0; q < 4; q++) acc[i][j][q] = 0.f;

    loadChunk(0, 0);
    for (int c = 0; c < nCh; c++) {
        int buf = c & 1;
        if (c + 1 < nCh) { loadChunk(c + 1, (c + 1) & 1); cp_wait<1>(); }
        else             { cp_wait<0>(); }
        __syncthreads();

        uint32_t aH = sAH + buf * TILEB, aL = sAL + buf * TILEB;
        uint32_t bH = sBH + buf * TILEB, bL = sBL + buf * TILEB;
        #pragma unroll
        for (int s = 0; s < 4; s++) {
            uint32_t ah[4][4], al[4][4], bh[2][4], bl[2][4];
            #pragma unroll
            for (int mt = 0; mt < 4; mt++) {
                uint32_t off = (uint32_t)(wm * 64 + mt * 16 + (lane & 15)) * ROWB
                             + (lane >> 4) * 16 + s * 32;
                ldsm4(ah[mt], aH + off);
                if (!hiOnly) ldsm4(al[mt], aL + off);
            }
            #pragma unroll
            for (int np = 0; np < 2; np++) {
                uint32_t off = (uint32_t)(wn * 32 + np * 16 + (lane & 15)) * ROWB
                             + (lane >> 4) * 16 + s * 32;
                ldsm4(bh[np], bH + off);
                if (!hiOnly) ldsm4(bl[np], bL + off);
            }
            #pragma unroll
            for (int mt = 0; mt < 4; mt++)
                #pragma unroll
                for (int nt = 0; nt < 4; nt++) {
                    int np = nt >> 1, half = nt & 1;
                    mma16816(acc[mt][nt], ah[mt], bh[np][half], bh[np][half + 2]);
                    if (!hiOnly) {
                        mma16816(acc[mt][nt], ah[mt], bl[np][half], bl[np][half + 2]);
                        mma16816(acc[mt][nt], al[mt], bh[np][half], bh[np][half + 2]);
                    }
                }
        }
        __syncthreads();
    }

    // ----------------- epilogue -----------------
    if (mode == 0) {
        #pragma unroll
        for (int mt = 0; mt < 4; mt++) {
            int rg = row0 + wm * 64 + mt * 16 + (lane >> 2);
            u64 bA = 0, bB = 0;
            #pragma unroll
            for (int nt = 0; nt < 4; nt++) {
                unsigned cb = (unsigned)(col0 + wn * 32 + nt * 8 + (lane & 3) * 2);
                u64 e;
                e = ((u64)fenc(acc[mt][nt][0]) << 32) | (unsigned)(~cb);       if (e > bA) bA = e;
                e = ((u64)fenc(acc[mt][nt][1]) << 32) | (unsigned)(~(cb + 1)); if (e > bA) bA = e;
                e = ((u64)fenc(acc[mt][nt][2]) << 32) | (unsigned)(~cb);       if (e > bB) bB = e;
                e = ((u64)fenc(acc[mt][nt][3]) << 32) | (unsigned)(~(cb + 1)); if (e > bB) bB = e;
            }
            #pragma unroll
            for (int off = 1; off <= 2; off <<= 1) {
                u64 oA = __shfl_xor_sync(~0u, bA, off);
                u64 oB = __shfl_xor_sync(~0u, bB, off);
                if (oA > bA) bA = oA;
                if (oB > bB) bB = oB;
            }
            if ((lane & 3) == 0) {
                atomicMax(&g_arg[rg], bA);
                atomicMax(&g_arg[rg + 8], bB);
            }
        }
    } else {
        #pragma unroll
        for (int mt = 0; mt < 4; mt++) {
            int rg = row0 + wm * 64 + mt * 16 + (lane >> 2);
            #pragma unroll
            for (int nt = 0; nt < 4; nt++) {
                int cg = col0 + wn * 32 + nt * 8 + (lane & 3) * 2;
                float2 lo = {acc[mt][nt][0], acc[mt][nt][1]};
                float2 hi = {acc[mt][nt][2], acc[mt][nt][3]};
                *(float2*)(outp + (size_t)rg * outW + cg)       = lo;
                *(float2*)(outp + (size_t)(rg + 8) * outW + cg) = hi;
            }
        }
    }
}

// ---------------- normalize codebook rows -> bf16 hi/lo ----------------
__global__ __launch_bounds__(128) void k_norm_m(const float* __restrict__ m,
                                                __nv_bfloat16* __restrict__ dh,
                                                __nv_bfloat16* __restrict__ dl) {
    int k = blockIdx.x, tid = threadIdx.x;
    float4 v = ((const float4*)(m + (size_t)k * CDIM))[tid];
    float ss = v.x*v.x + v.y*v.y + v.z*v.z + v.w*v.w;
    #pragma unroll
    for (int o = 16; o; o >>= 1) ss += __shfl_xor_sync(~0u, ss, o);
    __shared__ float sred[4]; __shared__ float sinv;
    if ((tid & 31) == 0) sred[tid >> 5] = ss;
    __syncthreads();
    if (tid == 0) sinv = 1.f / fmaxf(sqrtf(sred[0]+sred[1]+sred[2]+sred[3]), 1e-12f);
    __syncthreads();
    float inv = sinv;
    float o4[4] = {v.x*inv, v.y*inv, v.z*inv, v.w*inv};
    size_t base = (size_t)k * CDIM + tid * 4;
    #pragma unroll
    for (int j = 0; j < 4; j++) {
        __nv_bfloat16 h = __float2bfloat16(o4[j]);
        dh[base + j] = h;
        dl[base + j] = __float2bfloat16(o4[j] - __bfloat162float(h));
    }
}

// ---------------- EMA update + normalize -> bf16 hi/lo ----------------
__global__ __launch_bounds__(128) void k_update_m(const float* __restrict__ m) {
    int k = blockIdx.x, tid = threadIdx.x;
    float w = 0.001f / (g_cnt[k] + 1e-6f);
    float4 mv = ((const float4*)(m      + (size_t)k * CDIM))[tid];
    float4 ev = ((const float4*)(g_esum + (size_t)k * CDIM))[tid];
    float nv[4] = { mv.x*0.999f + ev.x*w, mv.y*0.999f + ev.y*w,
                    mv.z*0.999f + ev.z*w, mv.w*0.999f + ev.w*w };
    float ss = nv[0]*nv[0] + nv[1]*nv[1] + nv[2]*nv[2] + nv[3]*nv[3];
    #pragma unroll
    for (int o = 16; o; o >>= 1) ss += __shfl_xor_sync(~0u, ss, o);
    __shared__ float sred[4]; __shared__ float sinv;
    if ((tid & 31) == 0) sred[tid >> 5] = ss;
    __syncthreads();
    if (tid == 0) sinv = 1.f / fmaxf(sqrtf(sred[0]+sred[1]+sred[2]+sred[3]), 1e-12f);
    __syncthreads();
    float inv = sinv;
    size_t base = (size_t)k * CDIM + tid * 4;
    #pragma unroll
    for (int j = 0; j < 4; j++) {
        float v = nv[j] * inv;
        __nv_bfloat16 h = __float2bfloat16(v);
        g_m2h[base + j] = h;
        g_m2l[base + j] = __float2bfloat16(v - __bfloat162float(h));
    }
}

// ---------------- transpose std (K,V)->(V,K), bf16 hi/lo ----------------
__global__ void k_tstd(const float* __restrict__ s) {
    __shared__ float t[32][33];
    int v0 = blockIdx.x * 32, k0 = blockIdx.y * 32;
    int tx = threadIdx.x, ty = threadIdx.y;  // 32 x 8
    #pragma unroll
    for (int i = 0; i < 4; i++)
        t[ty + 8*i][tx] = s[(size_t)(k0 + ty + 8*i) * VC + v0 + tx];
    __syncthreads();
    #pragma unroll
    for (int i = 0; i < 4; i++) {
        float v = t[tx][ty + 8*i];
        __nv_bfloat16 h = __float2bfloat16(v);
        size_t o = (size_t)(v0 + ty + 8*i) * KN + k0 + tx;
        g_sth[o] = h;
        g_stl[o] = __float2bfloat16(v - __bfloat162float(h));
    }
}

// ---------------- transpose (b,c,h,w)->(n,c), normalize rows -> bf16 hi/lo ----------------
__global__ __launch_bounds__(256) void k_prep_x(const float* __restrict__ x) {
    __shared__ float s[CDIM][17];
    __shared__ float rsum[16][17];
    int bid = blockIdx.x;             // 0..2047
    int b   = bid >> 8;               // / 256
    int hw0 = (bid & 255) << 4;       // * 16
    int tx = threadIdx.x & 15, ty = threadIdx.x >> 4;
    const float* xb = x + (size_t)b * CDIM * HW + hw0;
    float ss = 0.f;
    for (int c = ty; c < CDIM; c += 16) {
        float v = xb[(size_t)c * HW + tx];
        s[c][tx] = v;
        ss += v * v;
    }
    rsum[ty][tx] = ss;
    __syncthreads();
    if (ty < 8) rsum[ty][tx] += rsum[ty + 8][tx];
    __syncthreads();
    if (ty < 4) rsum[ty][tx] += rsum[ty + 4][tx];
    __syncthreads();
    if (ty < 2) rsum[ty][tx] += rsum[ty + 2][tx];
    __syncthreads();
    if (ty == 0) {
        float norm = fmaxf(sqrtf(rsum[0][tx] + rsum[1][tx]), 1e-12f);
        g_xnorm[b * HW + hw0 + tx] = norm;
        rsum[0][tx] = 1.f / norm;
    }
    __syncthreads();
    int warp = threadIdx.x >> 5, lane = threadIdx.x & 31;
    #pragma unroll
    for (int q = 0; q < 2; q++) {
        int p = warp * 2 + q;
        float inv = rsum[0][p];
        size_t rbase = (size_t)(b * HW + hw0 + p) * CDIM;
        for (int c = lane; c < CDIM; c += 32) {
            float v = s[c][p] * inv;
            __nv_bfloat16 h = __float2bfloat16(v);
            g_xh[rbase + c] = h;
            g_xl[rbase + c] = __float2bfloat16(v - __bfloat162float(h));
        }
    }
}

// ---------------- zero segment buffers + argmax buffer ----------------
__global__ void k_zero() {
    int i = blockIdx.x * blockDim.x + threadIdx.x;
    if (i < KN * CDIM) g_esum[i] = 0.f;
    if (i < KN)        g_cnt[i]  = 0.f;
    if (i < NPIX)      g_arg[i]  = 0ull;
}

// ---------------- counts (decodes argmax) / scatter ----------------
__global__ void k_counts() {
    int n = blockIdx.x * blockDim.x + threadIdx.x;
    if (n < NPIX) {
        int idx = (int)(~(unsigned)(g_arg[n] & 0xFFFFFFFFull));
        g_ind[n] = idx;
        atomicAdd(&g_cnt[idx], 1.f);
    }
}
__global__ void k_scatter() {
    int i = blockIdx.x * blockDim.x + threadIdx.x;
    int n = i >> 9, c = i & 511;
    float v = (__bfloat162float(g_xh[(size_t)i]) + __bfloat162float(g_xl[(size_t)i]))
              * g_xnorm[n];
    atomicAdd(&g_esum[(size_t)g_ind[n] * CDIM + c], v);
}

// ---------------- softmax rows of score2 -> bf16 hi/lo prob ----------------
__global__ __launch_bounds__(256) void k_softmax(const float* __restrict__ s2) {
    int n = blockIdx.x, tid = threadIdx.x;
    float4 v = ((const float4*)(s2 + (size_t)n * KN))[tid];
    float mx = fmaxf(fmaxf(v.x, v.y), fmaxf(v.z, v.w));
    #pragma unroll
    for (int o = 16; o; o >>= 1) mx = fmaxf(mx, __shfl_xor_sync(~0u, mx, o));
    __shared__ float sm[8];
    if ((tid & 31) == 0) sm[tid >> 5] = mx;
    __syncthreads();
    if (tid < 32) {
        float t = (tid < 8) ? sm[tid] : -3.4e38f;
        #pragma unroll
        for (int o = 4; o; o >>= 1) t = fmaxf(t, __shfl_xor_sync(~0u, t, o));
        if (tid == 0) sm[0] = t;
    }
    __syncthreads();
    float M = sm[0];
    float e0 = __expf(v.x - M), e1 = __expf(v.y - M);
    float e2 = __expf(v.z - M), e3 = __expf(v.w - M);
    float ssum = e0 + e1 + e2 + e3;
    #pragma unroll
    for (int o = 16; o; o >>= 1) ssum += __shfl_xor_sync(~0u, ssum, o);
    __shared__ float sq[8];
    if ((tid & 31) == 0) sq[tid >> 5] = ssum;
    __syncthreads();
    if (tid < 32) {
        float t = (tid < 8) ? sq[tid] : 0.f;
        #pragma unroll
        for (int o = 4; o; o >>= 1) t += __shfl_xor_sync(~0u, t, o);
        if (tid == 0) sq[0] = t;
    }
    __syncthreads();
    float inv = 1.f / sq[0];
    float p[4] = {e0 * inv, e1 * inv, e2 * inv, e3 * inv};
    size_t base = (size_t)n * KN + tid * 4;
    #pragma unroll
    for (int j = 0; j < 4; j++) {
        __nv_bfloat16 h = __float2bfloat16(p[j]);
        g_ph[base + j] = h;
        g_pl[base + j] = __float2bfloat16(p[j] - __bfloat162float(h));
    }
}

// ---------------- launch ----------------
extern "C" void kernel_launch(void* const* d_in, const int* in_sizes, int n_in,
                              void* d_out, int out_size) {
    const float* x    = (const float*)d_in[0];   // (8,512,64,64)
    const float* m    = (const float*)d_in[1];   // (1024,512)
    const float* stdw = (const float*)d_in[2];   // (1024,512)
    float* out = (float*)d_out;

    __nv_bfloat16 *p_xh, *p_xl, *p_mh, *p_ml, *p_m2h, *p_m2l, *p_sth, *p_stl, *p_ph, *p_pl;
    float* p_prob;
    cudaGetSymbolAddress((void**)&p_xh,  g_xh);
    cudaGetSymbolAddress((void**)&p_xl,  g_xl);
    cudaGetSymbolAddress((void**)&p_mh,  g_mh);
    cudaGetSymbolAddress((void**)&p_ml,  g_ml);
    cudaGetSymbolAddress((void**)&p_m2h, g_m2h);
    cudaGetSymbolAddress((void**)&p_m2l, g_m2l);
    cudaGetSymbolAddress((void**)&p_sth, g_sth);
    cudaGetSymbolAddress((void**)&p_stl, g_stl);
    cudaGetSymbolAddress((void**)&p_ph,  g_ph);
    cudaGetSymbolAddress((void**)&p_pl,  g_pl);
    cudaGetSymbolAddress((void**)&p_prob, g_prob);

    cudaFuncSetAttribute(k_mma, cudaFuncAttributeMaxDynamicSharedMemorySize, SMEM_DYN);

    const long long OUT1 = (long long)NPIX * VC;
    const long long S2SZ = (long long)NPIX * KN;
    float* s2 = ((long long)out_size >= OUT1 + S2SZ) ? (out + OUT1) : p_prob;

    k_tstd   <<<dim3(VC / 32, KN / 32), dim3(32, 8)>>>(stdw);
    k_norm_m <<<KN, 128>>>(m, p_mh, p_ml);
    k_prep_x <<<2048, 256>>>(x);
    k_zero   <<<(KN * CDIM + 255) / 256, 256>>>();
    // GEMM1: score1 + argmax (hi-only pass); grid = (col tiles, row tiles)
    k_mma<<<dim3(KN / 128, NPIX / 128), 256, SMEM_DYN>>>(p_xh, p_xl, p_mh, p_ml,
                                                         CDIM, KN, 0, nullptr);
    k_counts <<<NPIX / 256, 256>>>();
    k_scatter<<<(NPIX * CDIM) / 256, 256>>>();
    k_update_m<<<KN, 128>>>(m);
    // GEMM2: score2 (3-pass hi/lo)
    k_mma<<<dim3(KN / 128, NPIX / 128), 256, SMEM_DYN>>>(p_xh, p_xl, p_m2h, p_m2l,
                                                         CDIM, KN, 1, s2);
    k_softmax<<<NPIX, 256>>>(s2);
    // GEMM3: out = prob @ std (3-pass hi/lo, operands prob(N,K), std^T(V,K))
    k_mma<<<dim3(VC / 128, NPIX / 128), 256, SMEM_DYN>>>(p_ph, p_pl, p_sth, p_stl,
                                                         KN, VC, 2, out);
}

// round 6
// speedup vs baseline: 3.1450x; 1.0326x over previous
#include <cuda_runtime.h>
#include <cuda_bf16.h>
#include <cstdint>
#include <cstddef>

#define NPIX 32768   // B*H*W = 8*64*64
#define CDIM 512
#define KN   1024
#define VC   512
#define HW   4096    // H*W

typedef unsigned long long u64;

// ---------------- scratch (static device globals; no allocation) ----------------
__device__ float g_xnorm[NPIX];                      // clipped norms
__device__ __nv_bfloat16 g_xh[(size_t)NPIX * CDIM];  // xn hi
__device__ __nv_bfloat16 g_xl[(size_t)NPIX * CDIM];  // xn lo
__device__ __nv_bfloat16 g_mh [KN * CDIM], g_ml [KN * CDIM];
__device__ __nv_bfloat16 g_m2h[KN * CDIM], g_m2l[KN * CDIM];
__device__ __nv_bfloat16 g_sth[(size_t)VC * KN], g_stl[(size_t)VC * KN]; // std^T hi/lo
__device__ __nv_bfloat16 g_ph[(size_t)NPIX * KN], g_pl[(size_t)NPIX * KN]; // prob hi/lo
__device__ float g_esum[KN * CDIM];
__device__ float g_cnt [KN];
__device__ u64   g_arg [NPIX];                       // encoded (score,~idx) argmax
__device__ float g_prob[(size_t)NPIX * KN];          // fp32 score2 fallback buffer

// ============================= PTX helpers (portable, sm_80+) =============================
__device__ __forceinline__ uint32_t smem_u32(const void* p) {
    uint32_t a;
    asm("{ .reg .u64 t; cvta.to.shared.u64 t, %1; cvt.u32.u64 %0, t; }" : "=r"(a) : "l"(p));
    return a;
}
__device__ __forceinline__ void cp16(uint32_t saddr, const void* gaddr) {
    asm volatile("cp.async.cg.shared.global [%0], [%1], 16;" :: "r"(saddr), "l"(gaddr));
}
__device__ __forceinline__ void cp_commit() {
    asm volatile("cp.async.commit_group;" ::: "memory");
}
template <int N>
__device__ __forceinline__ void cp_wait() {
    asm volatile("cp.async.wait_group %0;" :: "n"(N) : "memory");
}
__device__ __forceinline__ void ldsm4(uint32_t* r, uint32_t addr) {
    asm volatile("ldmatrix.sync.aligned.m8n8.x4.shared.b16 {%0,%1,%2,%3}, [%4];"
                 : "=r"(r[0]), "=r"(r[1]), "=r"(r[2]), "=r"(r[3]) : "r"(addr));
}
__device__ __forceinline__ void mma16816(float* d, const uint32_t* a, uint32_t b0, uint32_t b1) {
    asm volatile("mma.sync.aligned.m16n8k16.row.col.f32.bf16.bf16.f32 "
                 "{%0,%1,%2,%3}, {%4,%5,%6,%7}, {%8,%9}, {%0,%1,%2,%3};"
                 : "+f"(d[0]), "+f"(d[1]), "+f"(d[2]), "+f"(d[3])
                 : "r"(a[0]), "r"(a[1]), "r"(a[2]), "r"(a[3]), "r"(b0), "r"(b1));
}
__device__ __forceinline__ unsigned fenc(float f) {
    unsigned u = __float_as_uint(f);
    return (u & 0x80000000u) ? ~u : (u | 0x80000000u);
}

// SMEM: 2 buffers x {AH,AL,BH,BL}; rows x (64 bf16 = 128B + 16B pad)
// A tile: 128 rows, B tile: 256 rows
#define ROWB   144
#define ATILEB (128 * ROWB)         // 18432
#define BTILEB (256 * ROWB)         // 36864
// layout: AH[2] AL[2] BH[2] BL[2]
#define OFF_AH 0
#define OFF_AL (2 * ATILEB)                   // 36864
#define OFF_BH (4 * ATILEB)                   // 73728
#define OFF_BL (4 * ATILEB + 2 * BTILEB)      // 147456
#define SMEM_DYN (4 * ATILEB + 4 * BTILEB)    // 221184

// ===== HMMA GEMM: C tile (128 x 256) = A(M,Cd) @ B(Nc,Cd)^T, bf16 hi/lo, warp tile 64x64 =====
// blockIdx.x = COL tile (fast -> consecutive CTAs share the A row tile in L2)
// blockIdx.y = ROW tile
// mode 0: argmax over row -> g_arg (hi-only pass); mode 1/2: store fp32 to outp (width outW)
__global__ void __launch_bounds__(256, 1) k_mma(
    const __nv_bfloat16* __restrict__ Ah, const __nv_bfloat16* __restrict__ Al,
    const __nv_bfloat16* __restrict__ Bh, const __nv_bfloat16* __restrict__ Bl,
    int Cd, int outW, int mode, float* __restrict__ outp)
{
    extern __shared__ char smc[];
    const int tid = threadIdx.x, warp = tid >> 5, lane = tid & 31;
    const int wm = warp >> 2, wn = warp & 3;     // 2 x 4 warp grid, warp tile 64x64
    const int row0 = blockIdx.y * 128, col0 = blockIdx.x * 256;
    const bool hiOnly = (mode == 0);

    const uint32_t sBase = smem_u32(smc);

    const int nCh = Cd >> 6;   // chunks of 64 bf16 cols

    auto loadA = [&](const __nv_bfloat16* G, uint32_t sbase, int c0) {
        #pragma unroll
        for (int q = 0; q < 4; q++) {
            int u = tid + q * 256;           // 1024 16B units (128 rows x 8)
            int r = u >> 3, uo = u & 7;
            cp16(sbase + r * ROWB + uo * 16, G + (size_t)(row0 + r) * Cd + c0 + uo * 8);
        }
    };
    auto loadB = [&](const __nv_bfloat16* G, uint32_t sbase, int c0) {
        #pragma unroll
        for (int q = 0; q < 8; q++) {
            int u = tid + q * 256;           // 2048 16B units (256 rows x 8)
            int r = u >> 3, uo = u & 7;
            cp16(sbase + r * ROWB + uo * 16, G + (size_t)(col0 + r) * Cd + c0 + uo * 8);
        }
    };
    auto loadChunk = [&](int c, int buf) {
        int c0 = c << 6;
        loadA(Ah, sBase + OFF_AH + buf * ATILEB, c0);
        loadB(Bh, sBase + OFF_BH + buf * BTILEB, c0);
        if (!hiOnly) {
            loadA(Al, sBase + OFF_AL + buf * ATILEB, c0);
            loadB(Bl, sBase + OFF_BL + buf * BTILEB, c0);
        }
        cp_commit();
    };

    float acc[4][8][4];
    #pragma unroll
    for (int i = 0; i < 4; i++)
        #pragma unroll
        for (int j = 0; j < 8; j++)
            #pragma unroll
            for (int q = 0; q < 4; q++) acc[i][j][q] = 0.f;

    loadChunk(0, 0);
    for (int c = 0; c < nCh; c++) {
        int buf = c & 1;
        if (c + 1 < nCh) { loadChunk(c + 1, (c + 1) & 1); cp_wait<1>(); }
        else             { cp_wait<0>(); }
        __syncthreads();

        uint32_t aH = sBase + OFF_AH + buf * ATILEB, aL = sBase + OFF_AL + buf * ATILEB;
        uint32_t bH = sBase + OFF_BH + buf * BTILEB, bL = sBase + OFF_BL + buf * BTILEB;
        #pragma unroll
        for (int s = 0; s < 4; s++) {
            uint32_t ah[4][4], al[4][4], bh[4][4], bl[4][4];
            #pragma unroll
            for (int mt = 0; mt < 4; mt++) {
                uint32_t off = (uint32_t)(wm * 64 + mt * 16 + (lane & 15)) * ROWB
                             + (lane >> 4) * 16 + s * 32;
                ldsm4(ah[mt], aH + off);
                if (!hiOnly) ldsm4(al[mt], aL + off);
            }
            #pragma unroll
            for (int np = 0; np < 4; np++) {
                uint32_t off = (uint32_t)(wn * 64 + np * 16 + (lane & 15)) * ROWB
                             + (lane >> 4) * 16 + s * 32;
                ldsm4(bh[np], bH + off);
                if (!hiOnly) ldsm4(bl[np], bL + off);
            }
            #pragma unroll
            for (int mt = 0; mt < 4; mt++)
                #pragma unroll
                for (int nt = 0; nt < 8; nt++) {
                    int np = nt >> 1, half = nt & 1;
                    mma16816(acc[mt][nt], ah[mt], bh[np][half], bh[np][half + 2]);
                    if (!hiOnly) {
                        mma16816(acc[mt][nt], ah[mt], bl[np][half], bl[np][half + 2]);
                        mma16816(acc[mt][nt], al[mt], bh[np][half], bh[np][half + 2]);
                    }
                }
        }
        __syncthreads();
    }

    // ----------------- epilogue -----------------
    if (mode == 0) {
        #pragma unroll
        for (int mt = 0; mt < 4; mt++) {
            int rg = row0 + wm * 64 + mt * 16 + (lane >> 2);
            u64 bA = 0, bB = 0;
            #pragma unroll
            for (int nt = 0; nt < 8; nt++) {
                unsigned cb = (unsigned)(col0 + wn * 64 + nt * 8 + (lane & 3) * 2);
                u64 e;
                e = ((u64)fenc(acc[mt][nt][0]) << 32) | (unsigned)(~cb);       if (e > bA) bA = e;
                e = ((u64)fenc(acc[mt][nt][1]) << 32) | (unsigned)(~(cb + 1)); if (e > bA) bA = e;
                e = ((u64)fenc(acc[mt][nt][2]) << 32) | (unsigned)(~cb);       if (e > bB) bB = e;
                e = ((u64)fenc(acc[mt][nt][3]) << 32) | (unsigned)(~(cb + 1)); if (e > bB) bB = e;
            }
            #pragma unroll
            for (int off = 1; off <= 2; off <<= 1) {
                u64 oA = __shfl_xor_sync(~0u, bA, off);
                u64 oB = __shfl_xor_sync(~0u, bB, off);
                if (oA > bA) bA = oA;
                if (oB > bB) bB = oB;
            }
            if ((lane & 3) == 0) {
                atomicMax(&g_arg[rg], bA);
                atomicMax(&g_arg[rg + 8], bB);
            }
        }
    } else {
        #pragma unroll
        for (int mt = 0; mt < 4; mt++) {
            int rg = row0 + wm * 64 + mt * 16 + (lane >> 2);
            #pragma unroll
            for (int nt = 0; nt < 8; nt++) {
                int cg = col0 + wn * 64 + nt * 8 + (lane & 3) * 2;
                float2 lo = {acc[mt][nt][0], acc[mt][nt][1]};
                float2 hi = {acc[mt][nt][2], acc[mt][nt][3]};
                *(float2*)(outp + (size_t)rg * outW + cg)       = lo;
                *(float2*)(outp + (size_t)(rg + 8) * outW + cg) = hi;
            }
        }
    }
}

// ---------------- normalize codebook rows -> bf16 hi/lo ----------------
__global__ __launch_bounds__(128) void k_norm_m(const float* __restrict__ m,
                                                __nv_bfloat16* __restrict__ dh,
                                                __nv_bfloat16* __restrict__ dl) {
    int k = blockIdx.x, tid = threadIdx.x;
    float4 v = ((const float4*)(m + (size_t)k * CDIM))[tid];
    float ss = v.x*v.x + v.y*v.y + v.z*v.z + v.w*v.w;
    #pragma unroll
    for (int o = 16; o; o >>= 1) ss += __shfl_xor_sync(~0u, ss, o);
    __shared__ float sred[4]; __shared__ float sinv;
    if ((tid & 31) == 0) sred[tid >> 5] = ss;
    __syncthreads();
    if (tid == 0) sinv = 1.f / fmaxf(sqrtf(sred[0]+sred[1]+sred[2]+sred[3]), 1e-12f);
    __syncthreads();
    float inv = sinv;
    float o4[4] = {v.x*inv, v.y*inv, v.z*inv, v.w*inv};
    size_t base = (size_t)k * CDIM + tid * 4;
    #pragma unroll
    for (int j = 0; j < 4; j++) {
        __nv_bfloat16 h = __float2bfloat16(o4[j]);
        dh[base + j] = h;
        dl[base + j] = __float2bfloat16(o4[j] - __bfloat162float(h));
    }
}

// ---------------- EMA update + normalize -> bf16 hi/lo ----------------
__global__ __launch_bounds__(128) void k_update_m(const float* __restrict__ m) {
    int k = blockIdx.x, tid = threadIdx.x;
    float w = 0.001f / (g_cnt[k] + 1e-6f);
    float4 mv = ((const float4*)(m      + (size_t)k * CDIM))[tid];
    float4 ev = ((const float4*)(g_esum + (size_t)k * CDIM))[tid];
    float nv[4] = { mv.x*0.999f + ev.x*w, mv.y*0.999f + ev.y*w,
                    mv.z*0.999f + ev.z*w, mv.w*0.999f + ev.w*w };
    float ss = nv[0]*nv[0] + nv[1]*nv[1] + nv[2]*nv[2] + nv[3]*nv[3];
    #pragma unroll
    for (int o = 16; o; o >>= 1) ss += __shfl_xor_sync(~0u, ss, o);
    __shared__ float sred[4]; __shared__ float sinv;
    if ((tid & 31) == 0) sred[tid >> 5] = ss;
    __syncthreads();
    if (tid == 0) sinv = 1.f / fmaxf(sqrtf(sred[0]+sred[1]+sred[2]+sred[3]), 1e-12f);
    __syncthreads();
    float inv = sinv;
    size_t base = (size_t)k * CDIM + tid * 4;
    #pragma unroll
    for (int j = 0; j < 4; j++) {
        float v = nv[j] * inv;
        __nv_bfloat16 h = __float2bfloat16(v);
        g_m2h[base + j] = h;
        g_m2l[base + j] = __float2bfloat16(v - __bfloat162float(h));
    }
}

// ---------------- transpose std (K,V)->(V,K), bf16 hi/lo ----------------
__global__ void k_tstd(const float* __restrict__ s) {
    __shared__ float t[32][33];
    int v0 = blockIdx.x * 32, k0 = blockIdx.y * 32;
    int tx = threadIdx.x, ty = threadIdx.y;  // 32 x 8
    #pragma unroll
    for (int i = 0; i < 4; i++)
        t[ty + 8*i][tx] = s[(size_t)(k0 + ty + 8*i) * VC + v0 + tx];
    __syncthreads();
    #pragma unroll
    for (int i = 0; i < 4; i++) {
        float v = t[tx][ty + 8*i];
        __nv_bfloat16 h = __float2bfloat16(v);
        size_t o = (size_t)(v0 + ty + 8*i) * KN + k0 + tx;
        g_sth[o] = h;
        g_stl[o] = __float2bfloat16(v - __bfloat162float(h));
    }
}

// ---------------- transpose (b,c,h,w)->(n,c), normalize rows -> bf16 hi/lo ----------------
__global__ __launch_bounds__(256) void k_prep_x(const float* __restrict__ x) {
    __shared__ float s[CDIM][17];
    __shared__ float rsum[16][17];
    int bid = blockIdx.x;             // 0..2047
    int b   = bid >> 8;               // / 256
    int hw0 = (bid & 255) << 4;       // * 16
    int tx = threadIdx.x & 15, ty = threadIdx.x >> 4;
    const float* xb = x + (size_t)b * CDIM * HW + hw0;
    float ss = 0.f;
    for (int c = ty; c < CDIM; c += 16) {
        float v = xb[(size_t)c * HW + tx];
        s[c][tx] = v;
        ss += v * v;
    }
    rsum[ty][tx] = ss;
    __syncthreads();
    if (ty < 8) rsum[ty][tx] += rsum[ty + 8][tx];
    __syncthreads();
    if (ty < 4) rsum[ty][tx] += rsum[ty + 4][tx];
    __syncthreads();
    if (ty < 2) rsum[ty][tx] += rsum[ty + 2][tx];
    __syncthreads();
    if (ty == 0) {
        float norm = fmaxf(sqrtf(rsum[0][tx] + rsum[1][tx]), 1e-12f);
        g_xnorm[b * HW + hw0 + tx] = norm;
        rsum[0][tx] = 1.f / norm;
    }
    __syncthreads();
    int warp = threadIdx.x >> 5, lane = threadIdx.x & 31;
    #pragma unroll
    for (int q = 0; q < 2; q++) {
        int p = warp * 2 + q;
        float inv = rsum[0][p];
        size_t rbase = (size_t)(b * HW + hw0 + p) * CDIM;
        for (int c = lane; c < CDIM; c += 32) {
            float v = s[c][p] * inv;
            __nv_bfloat16 h = __float2bfloat16(v);
            g_xh[rbase + c] = h;
            g_xl[rbase + c] = __float2bfloat16(v - __bfloat162float(h));
        }
    }
}

// ---------------- zero segment buffers + argmax buffer ----------------
__global__ void k_zero() {
    int i = blockIdx.x * blockDim.x + threadIdx.x;
    if (i < KN * CDIM) g_esum[i] = 0.f;
    if (i < KN)        g_cnt[i]  = 0.f;
    if (i < NPIX)      g_arg[i]  = 0ull;
}

// ---------------- scatter (decodes argmax inline; c==0 lane also counts) ----------------
__global__ void k_scatter() {
    int i = blockIdx.x * blockDim.x + threadIdx.x;
    int n = i >> 9, c = i & 511;
    int idx = (int)(~(unsigned)(g_arg[n] & 0xFFFFFFFFull));
    float v = (__bfloat162float(g_xh[(size_t)i]) + __bfloat162float(g_xl[(size_t)i]))
              * g_xnorm[n];
    atomicAdd(&g_esum[(size_t)idx * CDIM + c], v);
    if (c == 0) atomicAdd(&g_cnt[idx], 1.f);
}

// ---------------- softmax rows of score2 -> bf16 hi/lo prob ----------------
__global__ __launch_bounds__(256) void k_softmax(const float* __restrict__ s2) {
    int n = blockIdx.x, tid = threadIdx.x;
    float4 v = ((const float4*)(s2 + (size_t)n * KN))[tid];
    float mx = fmaxf(fmaxf(v.x, v.y), fmaxf(v.z, v.w));
    #pragma unroll
    for (int o = 16; o; o >>= 1) mx = fmaxf(mx, __shfl_xor_sync(~0u, mx, o));
    __shared__ float sm[8];
    if ((tid & 31) == 0) sm[tid >> 5] = mx;
    __syncthreads();
    if (tid < 32) {
        float t = (tid < 8) ? sm[tid] : -3.4e38f;
        #pragma unroll
        for (int o = 4; o; o >>= 1) t = fmaxf(t, __shfl_xor_sync(~0u, t, o));
        if (tid == 0) sm[0] = t;
    }
    __syncthreads();
    float M = sm[0];
    float e0 = __expf(v.x - M), e1 = __expf(v.y - M);
    float e2 = __expf(v.z - M), e3 = __expf(v.w - M);
    float ssum = e0 + e1 + e2 + e3;
    #pragma unroll
    for (int o = 16; o; o >>= 1) ssum += __shfl_xor_sync(~0u, ssum, o);
    __shared__ float sq[8];
    if ((tid & 31) == 0) sq[tid >> 5] = ssum;
    __syncthreads();
    if (tid < 32) {
        float t = (tid < 8) ? sq[tid] : 0.f;
        #pragma unroll
        for (int o = 4; o; o >>= 1) t += __shfl_xor_sync(~0u, t, o);
        if (tid == 0) sq[0] = t;
    }
    __syncthreads();
    float inv = 1.f / sq[0];
    float p[4] = {e0 * inv, e1 * inv, e2 * inv, e3 * inv};
    size_t base = (size_t)n * KN + tid * 4;
    #pragma unroll
    for (int j = 0; j < 4; j++) {
        __nv_bfloat16 h = __float2bfloat16(p[j]);
        g_ph[base + j] = h;
        g_pl[base + j] = __float2bfloat16(p[j] - __bfloat162float(h));
    }
}

// ---------------- launch ----------------
extern "C" void kernel_launch(void* const* d_in, const int* in_sizes, int n_in,
                              void* d_out, int out_size) {
    const float* x    = (const float*)d_in[0];   // (8,512,64,64)
    const float* m    = (const float*)d_in[1];   // (1024,512)
    const float* stdw = (const float*)d_in[2];   // (1024,512)
    float* out = (float*)d_out;

    __nv_bfloat16 *p_xh, *p_xl, *p_mh, *p_ml, *p_m2h, *p_m2l, *p_sth, *p_stl, *p_ph, *p_pl;
    float* p_prob;
    cudaGetSymbolAddress((void**)&p_xh,  g_xh);
    cudaGetSymbolAddress((void**)&p_xl,  g_xl);
    cudaGetSymbolAddress((void**)&p_mh,  g_mh);
    cudaGetSymbolAddress((void**)&p_ml,  g_ml);
    cudaGetSymbolAddress((void**)&p_m2h, g_m2h);
    cudaGetSymbolAddress((void**)&p_m2l, g_m2l);
    cudaGetSymbolAddress((void**)&p_sth, g_sth);
    cudaGetSymbolAddress((void**)&p_stl, g_stl);
    cudaGetSymbolAddress((void**)&p_ph,  g_ph);
    cudaGetSymbolAddress((void**)&p_pl,  g_pl);
    cudaGetSymbolAddress((void**)&p_prob, g_prob);

    cudaFuncSetAttribute(k_mma, cudaFuncAttributeMaxDynamicSharedMemorySize, SMEM_DYN);

    const long long OUT1 = (long long)NPIX * VC;
    const long long S2SZ = (long long)NPIX * KN;
    float* s2 = ((long long)out_size >= OUT1 + S2SZ) ? (out + OUT1) : p_prob;

    // order chosen so the profiled launch (index 3) is the first k_mma
    k_norm_m <<<KN, 128>>>(m, p_mh, p_ml);
    k_prep_x <<<2048, 256>>>(x);
    k_zero   <<<(KN * CDIM + 255) / 256, 256>>>();
    // GEMM1: score1 + argmax (hi-only pass); grid = (col tiles, row tiles)
    k_mma<<<dim3(KN / 256, NPIX / 128), 256, SMEM_DYN>>>(p_xh, p_xl, p_mh, p_ml,
                                                         CDIM, KN, 0, nullptr);
    k_scatter<<<(NPIX * CDIM) / 256, 256>>>();
    k_update_m<<<KN, 128>>>(m);
    k_tstd   <<<dim3(VC / 32, KN / 32), dim3(32, 8)>>>(stdw);
    // GEMM2: score2 (3-pass hi/lo)
    k_mma<<<dim3(KN / 256, NPIX / 128), 256, SMEM_DYN>>>(p_xh, p_xl, p_m2h, p_m2l,
                                                         CDIM, KN, 1, s2);
    k_softmax<<<NPIX, 256>>>(s2);
    // GEMM3: out = prob @ std (3-pass hi/lo, operands prob(N,K), std^T(V,K))
    k_mma<<<dim3(VC / 256, NPIX / 128), 256, SMEM_DYN>>>(p_ph, p_pl, p_sth, p_stl,
                                                         KN, VC, 2, out);
}

// round 7
// speedup vs baseline: 3.9931x; 1.2697x over previous
#include <cuda_runtime.h>
#include <cuda_fp16.h>
#include <cstdint>
#include <cstddef>

#define NPIX 32768   // B*H*W = 8*64*64
#define CDIM 512
#define KN   1024
#define VC   512
#define HW   4096    // H*W

typedef unsigned long long u64;

// ---------------- scratch (static device globals; no allocation) ----------------
__device__ float g_xnorm[NPIX];                  // clipped norms
__device__ __half g_xh[(size_t)NPIX * CDIM];     // xn hi (fp16)
__device__ __half g_xl[(size_t)NPIX * CDIM];     // xn lo (fp16)
__device__ __half g_mh [KN * CDIM];              // mn hi (argmax pass is hi-only)
__device__ __half g_m2h[KN * CDIM], g_m2l[KN * CDIM];
__device__ __half g_sth[(size_t)VC * KN], g_stl[(size_t)VC * KN]; // std^T hi/lo
__device__ __half g_ph[(size_t)NPIX * KN], g_pl[(size_t)NPIX * KN]; // prob hi/lo
__device__ float g_esum[KN * CDIM];
__device__ float g_cnt [KN];
__device__ u64   g_arg [NPIX];                   // encoded (score,~idx) argmax
__device__ float g_prob[(size_t)NPIX * KN];      // fp32 score2 fallback buffer

// ============================= PTX helpers (portable, sm_80+) =============================
__device__ __forceinline__ uint32_t smem_u32(const void* p) {
    uint32_t a;
    asm("{ .reg .u64 t; cvta.to.shared.u64 t, %1; cvt.u32.u64 %0, t; }" : "=r"(a) : "l"(p));
    return a;
}
__device__ __forceinline__ void cp16(uint32_t saddr, const void* gaddr) {
    asm volatile("cp.async.cg.shared.global [%0], [%1], 16;" :: "r"(saddr), "l"(gaddr));
}
__device__ __forceinline__ void cp_commit() {
    asm volatile("cp.async.commit_group;" ::: "memory");
}
template <int N>
__device__ __forceinline__ void cp_wait() {
    asm volatile("cp.async.wait_group %0;" :: "n"(N) : "memory");
}
__device__ __forceinline__ void ldsm4(uint32_t* r, uint32_t addr) {
    asm volatile("ldmatrix.sync.aligned.m8n8.x4.shared.b16 {%0,%1,%2,%3}, [%4];"
                 : "=r"(r[0]), "=r"(r[1]), "=r"(r[2]), "=r"(r[3]) : "r"(addr));
}
__device__ __forceinline__ void mma16816(float* d, const uint32_t* a, uint32_t b0, uint32_t b1) {
    asm volatile("mma.sync.aligned.m16n8k16.row.col.f32.f16.f16.f32 "
                 "{%0,%1,%2,%3}, {%4,%5,%6,%7}, {%8,%9}, {%0,%1,%2,%3};"
                 : "+f"(d[0]), "+f"(d[1]), "+f"(d[2]), "+f"(d[3])
                 : "r"(a[0]), "r"(a[1]), "r"(a[2]), "r"(a[3]), "r"(b0), "r"(b1));
}
__device__ __forceinline__ unsigned fenc(float f) {
    unsigned u = __float_as_uint(f);
    return (u & 0x80000000u) ? ~u : (u | 0x80000000u);
}

// SMEM: AH[2], BH[2], BL[2]; rows x (64 fp16 = 128B + 16B pad)
// A tile: 128 rows, B tile: 256 rows
#define ROWB   144
#define ATILEB (128 * ROWB)         // 18432
#define BTILEB (256 * ROWB)         // 36864
#define OFF_AH 0
#define OFF_BH (2 * ATILEB)                   // 36864
#define OFF_BL (2 * ATILEB + 2 * BTILEB)      // 110592
#define SMEM_DYN (2 * ATILEB + 4 * BTILEB)    // 184320

// ===== HMMA GEMM: C tile (128 x 256) = A(M,Cd) @ B(Nc,Cd)^T, fp16, warp tile 64x64 =====
// mode 0: 1-pass (Ah*Bh) + row argmax -> g_arg
// mode 1/2: 2-pass (Ah*Bh + Ah*Bl), store fp32 rows to outp (width outW)
__global__ void __launch_bounds__(256, 1) k_mma(
    const __half* __restrict__ Ah,
    const __half* __restrict__ Bh, const __half* __restrict__ Bl,
    int Cd, int outW, int mode, float* __restrict__ outp)
{
    extern __shared__ char smc[];
    const int tid = threadIdx.x, warp = tid >> 5, lane = tid & 31;
    const int wm = warp >> 2, wn = warp & 3;     // 2 x 4 warp grid, warp tile 64x64
    const int row0 = blockIdx.y * 128, col0 = blockIdx.x * 256;
    const bool hiOnly = (mode == 0);

    const uint32_t sBase = smem_u32(smc);
    const int nCh = Cd >> 6;   // chunks of 64 fp16 cols

    auto loadA = [&](const __half* G, uint32_t sbase, int c0) {
        #pragma unroll
        for (int q = 0; q < 4; q++) {
            int u = tid + q * 256;           // 1024 16B units (128 rows x 8)
            int r = u >> 3, uo = u & 7;
            cp16(sbase + r * ROWB + uo * 16, G + (size_t)(row0 + r) * Cd + c0 + uo * 8);
        }
    };
    auto loadB = [&](const __half* G, uint32_t sbase, int c0) {
        #pragma unroll
        for (int q = 0; q < 8; q++) {
            int u = tid + q * 256;           // 2048 16B units (256 rows x 8)
            int r = u >> 3, uo = u & 7;
            cp16(sbase + r * ROWB + uo * 16, G + (size_t)(col0 + r) * Cd + c0 + uo * 8);
        }
    };
    auto loadChunk = [&](int c, int buf) {
        int c0 = c << 6;
        loadA(Ah, sBase + OFF_AH + buf * ATILEB, c0);
        loadB(Bh, sBase + OFF_BH + buf * BTILEB, c0);
        if (!hiOnly) loadB(Bl, sBase + OFF_BL + buf * BTILEB, c0);
        cp_commit();
    };

    float acc[4][8][4];
    #pragma unroll
    for (int i = 0; i < 4; i++)
        #pragma unroll
        for (int j = 0; j < 8; j++)
            #pragma unroll
            for (int q = 0; q < 4; q++) acc[i][j][q] = 0.f;

    loadChunk(0, 0);
    for (int c = 0; c < nCh; c++) {
        int buf = c & 1;
        if (c + 1 < nCh) { loadChunk(c + 1, (c + 1) & 1); cp_wait<1>(); }
        else             { cp_wait<0>(); }
        __syncthreads();

        uint32_t aH = sBase + OFF_AH + buf * ATILEB;
        uint32_t bH = sBase + OFF_BH + buf * BTILEB;
        uint32_t bL = sBase + OFF_BL + buf * BTILEB;
        #pragma unroll
        for (int s = 0; s < 4; s++) {
            uint32_t ah[4][4], bh[4][4], bl[4][4];
            #pragma unroll
            for (int mt = 0; mt < 4; mt++) {
                uint32_t off = (uint32_t)(wm * 64 + mt * 16 + (lane & 15)) * ROWB
                             + (lane >> 4) * 16 + s * 32;
                ldsm4(ah[mt], aH + off);
            }
            #pragma unroll
            for (int np = 0; np < 4; np++) {
                uint32_t off = (uint32_t)(wn * 64 + np * 16 + (lane & 15)) * ROWB
                             + (lane >> 4) * 16 + s * 32;
                ldsm4(bh[np], bH + off);
                if (!hiOnly) ldsm4(bl[np], bL + off);
            }
            #pragma unroll
            for (int mt = 0; mt < 4; mt++)
                #pragma unroll
                for (int nt = 0; nt < 8; nt++) {
                    int np = nt >> 1, half = nt & 1;
                    mma16816(acc[mt][nt], ah[mt], bh[np][half], bh[np][half + 2]);
                    if (!hiOnly)
                        mma16816(acc[mt][nt], ah[mt], bl[np][half], bl[np][half + 2]);
                }
        }
        __syncthreads();
    }

    // ----------------- epilogue -----------------
    if (mode == 0) {
        #pragma unroll
        for (int mt = 0; mt < 4; mt++) {
            int rg = row0 + wm * 64 + mt * 16 + (lane >> 2);
            u64 bA = 0, bB = 0;
            #pragma unroll
            for (int nt = 0; nt < 8; nt++) {
                unsigned cb = (unsigned)(col0 + wn * 64 + nt * 8 + (lane & 3) * 2);
                u64 e;
                e = ((u64)fenc(acc[mt][nt][0]) << 32) | (unsigned)(~cb);       if (e > bA) bA = e;
                e = ((u64)fenc(acc[mt][nt][1]) << 32) | (unsigned)(~(cb + 1)); if (e > bA) bA = e;
                e = ((u64)fenc(acc[mt][nt][2]) << 32) | (unsigned)(~cb);       if (e > bB) bB = e;
                e = ((u64)fenc(acc[mt][nt][3]) << 32) | (unsigned)(~(cb + 1)); if (e > bB) bB = e;
            }
            #pragma unroll
            for (int off = 1; off <= 2; off <<= 1) {
                u64 oA = __shfl_xor_sync(~0u, bA, off);
                u64 oB = __shfl_xor_sync(~0u, bB, off);
                if (oA > bA) bA = oA;
                if (oB > bB) bB = oB;
            }
            if ((lane & 3) == 0) {
                atomicMax(&g_arg[rg], bA);
                atomicMax(&g_arg[rg + 8], bB);
            }
        }
    } else {
        #pragma unroll
        for (int mt = 0; mt < 4; mt++) {
            int rg = row0 + wm * 64 + mt * 16 + (lane >> 2);
            #pragma unroll
            for (int nt = 0; nt < 8; nt++) {
                int cg = col0 + wn * 64 + nt * 8 + (lane & 3) * 2;
                float2 lo = {acc[mt][nt][0], acc[mt][nt][1]};
                float2 hi = {acc[mt][nt][2], acc[mt][nt][3]};
                *(float2*)(outp + (size_t)rg * outW + cg)       = lo;
                *(float2*)(outp + (size_t)(rg + 8) * outW + cg) = hi;
            }
        }
    }
}

// ---------------- normalize codebook rows -> fp16 hi (argmax pass needs only hi) ----------
__global__ __launch_bounds__(128) void k_norm_m(const float* __restrict__ m,
                                                __half* __restrict__ dh) {
    int k = blockIdx.x, tid = threadIdx.x;
    float4 v = ((const float4*)(m + (size_t)k * CDIM))[tid];
    float ss = v.x*v.x + v.y*v.y + v.z*v.z + v.w*v.w;
    #pragma unroll
    for (int o = 16; o; o >>= 1) ss += __shfl_xor_sync(~0u, ss, o);
    __shared__ float sred[4]; __shared__ float sinv;
    if ((tid & 31) == 0) sred[tid >> 5] = ss;
    __syncthreads();
    if (tid == 0) sinv = 1.f / fmaxf(sqrtf(sred[0]+sred[1]+sred[2]+sred[3]), 1e-12f);
    __syncthreads();
    float inv = sinv;
    float o4[4] = {v.x*inv, v.y*inv, v.z*inv, v.w*inv};
    size_t base = (size_t)k * CDIM + tid * 4;
    #pragma unroll
    for (int j = 0; j < 4; j++) dh[base + j] = __float2half_rn(o4[j]);
}

// ---------------- EMA update + normalize -> fp16 hi/lo ----------------
__global__ __launch_bounds__(128) void k_update_m(const float* __restrict__ m) {
    int k = blockIdx.x, tid = threadIdx.x;
    float w = 0.001f / (g_cnt[k] + 1e-6f);
    float4 mv = ((const float4*)(m      + (size_t)k * CDIM))[tid];
    float4 ev = ((const float4*)(g_esum + (size_t)k * CDIM))[tid];
    float nv[4] = { mv.x*0.999f + ev.x*w, mv.y*0.999f + ev.y*w,
                    mv.z*0.999f + ev.z*w, mv.w*0.999f + ev.w*w };
    float ss = nv[0]*nv[0] + nv[1]*nv[1] + nv[2]*nv[2] + nv[3]*nv[3];
    #pragma unroll
    for (int o = 16; o; o >>= 1) ss += __shfl_xor_sync(~0u, ss, o);
    __shared__ float sred[4]; __shared__ float sinv;
    if ((tid & 31) == 0) sred[tid >> 5] = ss;
    __syncthreads();
    if (tid == 0) sinv = 1.f / fmaxf(sqrtf(sred[0]+sred[1]+sred[2]+sred[3]), 1e-12f);
    __syncthreads();
    float inv = sinv;
    size_t base = (size_t)k * CDIM + tid * 4;
    #pragma unroll
    for (int j = 0; j < 4; j++) {
        float v = nv[j] * inv;
        __half h = __float2half_rn(v);
        g_m2h[base + j] = h;
        g_m2l[base + j] = __float2half_rn(v - __half2float(h));
    }
}

// ---------------- transpose std (K,V)->(V,K), fp16 hi/lo ----------------
__global__ void k_tstd(const float* __restrict__ s) {
    __shared__ float t[32][33];
    int v0 = blockIdx.x * 32, k0 = blockIdx.y * 32;
    int tx = threadIdx.x, ty = threadIdx.y;  // 32 x 8
    #pragma unroll
    for (int i = 0; i < 4; i++)
        t[ty + 8*i][tx] = s[(size_t)(k0 + ty + 8*i) * VC + v0 + tx];
    __syncthreads();
    #pragma unroll
    for (int i = 0; i < 4; i++) {
        float v = t[tx][ty + 8*i];
        __half h = __float2half_rn(v);
        size_t o = (size_t)(v0 + ty + 8*i) * KN + k0 + tx;
        g_sth[o] = h;
        g_stl[o] = __float2half_rn(v - __half2float(h));
    }
}

// ---------------- transpose (b,c,h,w)->(n,c), normalize rows -> fp16 hi/lo ----------------
__global__ __launch_bounds__(256) void k_prep_x(const float* __restrict__ x) {
    __shared__ float s[CDIM][17];
    __shared__ float rsum[16][17];
    int bid = blockIdx.x;             // 0..2047
    int b   = bid >> 8;               // / 256
    int hw0 = (bid & 255) << 4;       // * 16
    int tx = threadIdx.x & 15, ty = threadIdx.x >> 4;
    const float* xb = x + (size_t)b * CDIM * HW + hw0;
    float ss = 0.f;
    for (int c = ty; c < CDIM; c += 16) {
        float v = xb[(size_t)c * HW + tx];
        s[c][tx] = v;
        ss += v * v;
    }
    rsum[ty][tx] = ss;
    __syncthreads();
    if (ty < 8) rsum[ty][tx] += rsum[ty + 8][tx];
    __syncthreads();
    if (ty < 4) rsum[ty][tx] += rsum[ty + 4][tx];
    __syncthreads();
    if (ty < 2) rsum[ty][tx] += rsum[ty + 2][tx];
    __syncthreads();
    if (ty == 0) {
        float norm = fmaxf(sqrtf(rsum[0][tx] + rsum[1][tx]), 1e-12f);
        g_xnorm[b * HW + hw0 + tx] = norm;
        rsum[0][tx] = 1.f / norm;
    }
    __syncthreads();
    int warp = threadIdx.x >> 5, lane = threadIdx.x & 31;
    #pragma unroll
    for (int q = 0; q < 2; q++) {
        int p = warp * 2 + q;
        float inv = rsum[0][p];
        size_t rbase = (size_t)(b * HW + hw0 + p) * CDIM;
        for (int c = lane; c < CDIM; c += 32) {
            float v = s[c][p] * inv;
            __half h = __float2half_rn(v);
            g_xh[rbase + c] = h;
            g_xl[rbase + c] = __float2half_rn(v - __half2float(h));
        }
    }
}

// ---------------- zero segment buffers + argmax buffer ----------------
__global__ void k_zero() {
    int i = blockIdx.x * blockDim.x + threadIdx.x;
    if (i < KN * CDIM) g_esum[i] = 0.f;
    if (i < KN)        g_cnt[i]  = 0.f;
    if (i < NPIX)      g_arg[i]  = 0ull;
}

// ---------------- scatter (decodes argmax inline; c==0 lane also counts) ----------------
__global__ void k_scatter() {
    int i = blockIdx.x * blockDim.x + threadIdx.x;
    int n = i >> 9, c = i & 511;
    int idx = (int)(~(unsigned)(g_arg[n] & 0xFFFFFFFFull));
    float v = (__half2float(g_xh[(size_t)i]) + __half2float(g_xl[(size_t)i]))
              * g_xnorm[n];
    atomicAdd(&g_esum[(size_t)idx * CDIM + c], v);
    if (c == 0) atomicAdd(&g_cnt[idx], 1.f);
}

// ---------------- softmax rows of score2 -> fp16 hi/lo prob ----------------
__global__ __launch_bounds__(256) void k_softmax(const float* __restrict__ s2) {
    int n = blockIdx.x, tid = threadIdx.x;
    float4 v = ((const float4*)(s2 + (size_t)n * KN))[tid];
    float mx = fmaxf(fmaxf(v.x, v.y), fmaxf(v.z, v.w));
    #pragma unroll
    for (int o = 16; o; o >>= 1) mx = fmaxf(mx, __shfl_xor_sync(~0u, mx, o));
    __shared__ float sm[8];
    if ((tid & 31) == 0) sm[tid >> 5] = mx;
    __syncthreads();
    if (tid < 32) {
        float t = (tid < 8) ? sm[tid] : -3.4e38f;
        #pragma unroll
        for (int o = 4; o; o >>= 1) t = fmaxf(t, __shfl_xor_sync(~0u, t, o));
        if (tid == 0) sm[0] = t;
    }
    __syncthreads();
    float M = sm[0];
    float e0 = __expf(v.x - M), e1 = __expf(v.y - M);
    float e2 = __expf(v.z - M), e3 = __expf(v.w - M);
    float ssum = e0 + e1 + e2 + e3;
    #pragma unroll
    for (int o = 16; o; o >>= 1) ssum += __shfl_xor_sync(~0u, ssum, o);
    __shared__ float sq[8];
    if ((tid & 31) == 0) sq[tid >> 5] = ssum;
    __syncthreads();
    if (tid < 32) {
        float t = (tid < 8) ? sq[tid] : 0.f;
        #pragma unroll
        for (int o = 4; o; o >>= 1) t += __shfl_xor_sync(~0u, t, o);
        if (tid == 0) sq[0] = t;
    }
    __syncthreads();
    float inv = 1.f / sq[0];
    float p[4] = {e0 * inv, e1 * inv, e2 * inv, e3 * inv};
    size_t base = (size_t)n * KN + tid * 4;
    #pragma unroll
    for (int j = 0; j < 4; j++) {
        __half h = __float2half_rn(p[j]);
        g_ph[base + j] = h;
        g_pl[base + j] = __float2half_rn(p[j] - __half2float(h));
    }
}

// ---------------- launch ----------------
extern "C" void kernel_launch(void* const* d_in, const int* in_sizes, int n_in,
                              void* d_out, int out_size) {
    const float* x    = (const float*)d_in[0];   // (8,512,64,64)
    const float* m    = (const float*)d_in[1];   // (1024,512)
    const float* stdw = (const float*)d_in[2];   // (1024,512)
    float* out = (float*)d_out;

    __half *p_xh, *p_mh, *p_m2h, *p_m2l, *p_sth, *p_stl, *p_ph, *p_pl;
    float* p_prob;
    cudaGetSymbolAddress((void**)&p_xh,  g_xh);
    cudaGetSymbolAddress((void**)&p_mh,  g_mh);
    cudaGetSymbolAddress((void**)&p_m2h, g_m2h);
    cudaGetSymbolAddress((void**)&p_m2l, g_m2l);
    cudaGetSymbolAddress((void**)&p_sth, g_sth);
    cudaGetSymbolAddress((void**)&p_stl, g_stl);
    cudaGetSymbolAddress((void**)&p_ph,  g_ph);
    cudaGetSymbolAddress((void**)&p_pl,  g_pl);
    cudaGetSymbolAddress((void**)&p_prob, g_prob);

    cudaFuncSetAttribute(k_mma, cudaFuncAttributeMaxDynamicSharedMemorySize, SMEM_DYN);

    const long long OUT1 = (long long)NPIX * VC;
    const long long S2SZ = (long long)NPIX * KN;
    float* s2 = ((long long)out_size >= OUT1 + S2SZ) ? (out + OUT1) : p_prob;

    k_norm_m <<<KN, 128>>>(m, p_mh);
    k_prep_x <<<2048, 256>>>(x);
    k_zero   <<<(KN * CDIM + 255) / 256, 256>>>();
    // GEMM1: score1 + argmax (1-pass fp16 hi); grid = (col tiles, row tiles)
    k_mma<<<dim3(KN / 256, NPIX / 128), 256, SMEM_DYN>>>(p_xh, p_mh, nullptr,
                                                         CDIM, KN, 0, nullptr);
    k_scatter<<<(NPIX * CDIM) / 256, 256>>>();
    k_update_m<<<KN, 128>>>(m);
    k_tstd   <<<dim3(VC / 32, KN / 32), dim3(32, 8)>>>(stdw);
    // GEMM2: score2 (2-pass: Ah*Bh + Ah*Bl)
    k_mma<<<dim3(KN / 256, NPIX / 128), 256, SMEM_DYN>>>(p_xh, p_m2h, p_m2l,
                                                         CDIM, KN, 1, s2);
    k_softmax<<<NPIX, 256>>>(s2);
    // GEMM3: out = prob @ std (2-pass, operands prob(N,K), std^T(V,K))
    k_mma<<<dim3(VC / 256, NPIX / 128), 256, SMEM_DYN>>>(p_ph, p_sth, p_stl,
                                                         KN, VC, 2, out);
}

// round 8
// speedup vs baseline: 4.1126x; 1.0299x over previous
#include <cuda_runtime.h>
#include <cuda_fp16.h>
#include <cstdint>
#include <cstddef>

#define NPIX 32768   // B*H*W = 8*64*64
#define CDIM 512
#define KN   1024
#define VC   512
#define HW   4096    // H*W

typedef unsigned long long u64;

// ---------------- scratch (static device globals; no allocation) ----------------
__device__ __half g_xh[(size_t)NPIX * CDIM];     // xn hi (fp16)
__device__ __half g_mh [KN * CDIM];              // mn hi (argmax pass is hi-only)
__device__ __half g_m2h[KN * CDIM], g_m2l[KN * CDIM];
__device__ __half g_sth[(size_t)VC * KN], g_stl[(size_t)VC * KN]; // std^T hi/lo
__device__ __half g_ph[(size_t)NPIX * KN], g_pl[(size_t)NPIX * KN]; // prob hi/lo
__device__ float g_esum[KN * CDIM];
__device__ float g_cnt [KN];
__device__ u64   g_arg [NPIX];                   // encoded (score,~idx) argmax
__device__ float g_prob[(size_t)NPIX * KN];      // fp32 score2 fallback buffer

// ============================= PTX helpers (portable, sm_80+) =============================
__device__ __forceinline__ uint32_t smem_u32(const void* p) {
    uint32_t a;
    asm("{ .reg .u64 t; cvta.to.shared.u64 t, %1; cvt.u32.u64 %0, t; }" : "=r"(a) : "l"(p));
    return a;
}
__device__ __forceinline__ void cp16(uint32_t saddr, const void* gaddr) {
    asm volatile("cp.async.cg.shared.global [%0], [%1], 16;" :: "r"(saddr), "l"(gaddr));
}
__device__ __forceinline__ void cp_commit() {
    asm volatile("cp.async.commit_group;" ::: "memory");
}
template <int N>
__device__ __forceinline__ void cp_wait() {
    asm volatile("cp.async.wait_group %0;" :: "n"(N) : "memory");
}
__device__ __forceinline__ void ldsm4(uint32_t* r, uint32_t addr) {
    asm volatile("ldmatrix.sync.aligned.m8n8.x4.shared.b16 {%0,%1,%2,%3}, [%4];"
                 : "=r"(r[0]), "=r"(r[1]), "=r"(r[2]), "=r"(r[3]) : "r"(addr));
}
__device__ __forceinline__ void mma16816(float* d, const uint32_t* a, uint32_t b0, uint32_t b1) {
    asm volatile("mma.sync.aligned.m16n8k16.row.col.f32.f16.f16.f32 "
                 "{%0,%1,%2,%3}, {%4,%5,%6,%7}, {%8,%9}, {%0,%1,%2,%3};"
                 : "+f"(d[0]), "+f"(d[1]), "+f"(d[2]), "+f"(d[3])
                 : "r"(a[0]), "r"(a[1]), "r"(a[2]), "r"(a[3]), "r"(b0), "r"(b1));
}
__device__ __forceinline__ unsigned fenc(float f) {
    unsigned u = __float_as_uint(f);
    return (u & 0x80000000u) ? ~u : (u | 0x80000000u);
}

// SMEM: AH[2], BH[2], BL[2]; rows x (64 fp16 = 128B + 16B pad)
#define ROWB   144
#define ATILEB (128 * ROWB)         // 18432
#define BTILEB (256 * ROWB)         // 36864
#define OFF_AH 0
#define OFF_BH (2 * ATILEB)                   // 36864
#define OFF_BL (2 * ATILEB + 2 * BTILEB)      // 110592
#define SMEM_DYN (2 * ATILEB + 4 * BTILEB)    // 184320

// ===== HMMA GEMM: C tile (128 x 256) = A(M,Cd) @ B(Nc,Cd)^T, fp16, warp tile 64x64 =====
// mode 0: 1-pass (Ah*Bh) + row argmax -> g_arg
// mode 1/2: 2-pass (Ah*Bh + Ah*Bl), store fp32 rows to outp (width outW)
__global__ void __launch_bounds__(256, 1) k_mma(
    const __half* __restrict__ Ah,
    const __half* __restrict__ Bh, const __half* __restrict__ Bl,
    int Cd, int outW, int mode, float* __restrict__ outp)
{
    extern __shared__ char smc[];
    const int tid = threadIdx.x, warp = tid >> 5, lane = tid & 31;
    const int wm = warp >> 2, wn = warp & 3;     // 2 x 4 warp grid, warp tile 64x64
    const int row0 = blockIdx.y * 128, col0 = blockIdx.x * 256;
    const bool hiOnly = (mode == 0);

    const uint32_t sBase = smem_u32(smc);
    const int nCh = Cd >> 6;   // chunks of 64 fp16 cols

    auto loadA = [&](const __half* G, uint32_t sbase, int c0) {
        #pragma unroll
        for (int q = 0; q < 4; q++) {
            int u = tid + q * 256;           // 1024 16B units (128 rows x 8)
            int r = u >> 3, uo = u & 7;
            cp16(sbase + r * ROWB + uo * 16, G + (size_t)(row0 + r) * Cd + c0 + uo * 8);
        }
    };
    auto loadB = [&](const __half* G, uint32_t sbase, int c0) {
        #pragma unroll
        for (int q = 0; q < 8; q++) {
            int u = tid + q * 256;           // 2048 16B units (256 rows x 8)
            int r = u >> 3, uo = u & 7;
            cp16(sbase + r * ROWB + uo * 16, G + (size_t)(col0 + r) * Cd + c0 + uo * 8);
        }
    };
    auto loadChunk = [&](int c, int buf) {
        int c0 = c << 6;
        loadA(Ah, sBase + OFF_AH + buf * ATILEB, c0);
        loadB(Bh, sBase + OFF_BH + buf * BTILEB, c0);
        if (!hiOnly) loadB(Bl, sBase + OFF_BL + buf * BTILEB, c0);
        cp_commit();
    };

    float acc[4][8][4];
    #pragma unroll
    for (int i = 0; i < 4; i++)
        #pragma unroll
        for (int j = 0; j < 8; j++)
            #pragma unroll
            for (int q = 0; q < 4; q++) acc[i][j][q] = 0.f;

    loadChunk(0, 0);
    for (int c = 0; c < nCh; c++) {
        int buf = c & 1;
        if (c + 1 < nCh) { loadChunk(c + 1, (c + 1) & 1); cp_wait<1>(); }
        else             { cp_wait<0>(); }
        __syncthreads();

        uint32_t aH = sBase + OFF_AH + buf * ATILEB;
        uint32_t bH = sBase + OFF_BH + buf * BTILEB;
        uint32_t bL = sBase + OFF_BL + buf * BTILEB;
        #pragma unroll
        for (int s = 0; s < 4; s++) {
            uint32_t ah[4][4], bh[4][4], bl[4][4];
            #pragma unroll
            for (int mt = 0; mt < 4; mt++) {
                uint32_t off = (uint32_t)(wm * 64 + mt * 16 + (lane & 15)) * ROWB
                             + (lane >> 4) * 16 + s * 32;
                ldsm4(ah[mt], aH + off);
            }
            #pragma unroll
            for (int np = 0; np < 4; np++) {
                uint32_t off = (uint32_t)(wn * 64 + np * 16 + (lane & 15)) * ROWB
                             + (lane >> 4) * 16 + s * 32;
                ldsm4(bh[np], bH + off);
                if (!hiOnly) ldsm4(bl[np], bL + off);
            }
            #pragma unroll
            for (int mt = 0; mt < 4; mt++)
                #pragma unroll
                for (int nt = 0; nt < 8; nt++) {
                    int np = nt >> 1, half = nt & 1;
                    mma16816(acc[mt][nt], ah[mt], bh[np][half], bh[np][half + 2]);
                    if (!hiOnly)
                        mma16816(acc[mt][nt], ah[mt], bl[np][half], bl[np][half + 2]);
                }
        }
        __syncthreads();
    }

    // ----------------- epilogue -----------------
    if (mode == 0) {
        #pragma unroll
        for (int mt = 0; mt < 4; mt++) {
            int rg = row0 + wm * 64 + mt * 16 + (lane >> 2);
            u64 bA = 0, bB = 0;
            #pragma unroll
            for (int nt = 0; nt < 8; nt++) {
                unsigned cb = (unsigned)(col0 + wn * 64 + nt * 8 + (lane & 3) * 2);
                u64 e;
                e = ((u64)fenc(acc[mt][nt][0]) << 32) | (unsigned)(~cb);       if (e > bA) bA = e;
                e = ((u64)fenc(acc[mt][nt][1]) << 32) | (unsigned)(~(cb + 1)); if (e > bA) bA = e;
                e = ((u64)fenc(acc[mt][nt][2]) << 32) | (unsigned)(~cb);       if (e > bB) bB = e;
                e = ((u64)fenc(acc[mt][nt][3]) << 32) | (unsigned)(~(cb + 1)); if (e > bB) bB = e;
            }
            #pragma unroll
            for (int off = 1; off <= 2; off <<= 1) {
                u64 oA = __shfl_xor_sync(~0u, bA, off);
                u64 oB = __shfl_xor_sync(~0u, bB, off);
                if (oA > bA) bA = oA;
                if (oB > bB) bB = oB;
            }
            if ((lane & 3) == 0) {
                atomicMax(&g_arg[rg], bA);
                atomicMax(&g_arg[rg + 8], bB);
            }
        }
    } else {
        #pragma unroll
        for (int mt = 0; mt < 4; mt++) {
            int rg = row0 + wm * 64 + mt * 16 + (lane >> 2);
            #pragma unroll
            for (int nt = 0; nt < 8; nt++) {
                int cg = col0 + wn * 64 + nt * 8 + (lane & 3) * 2;
                float2 lo = {acc[mt][nt][0], acc[mt][nt][1]};
                float2 hi = {acc[mt][nt][2], acc[mt][nt][3]};
                *(float2*)(outp + (size_t)rg * outW + cg)       = lo;
                *(float2*)(outp + (size_t)(rg + 8) * outW + cg) = hi;
            }
        }
    }
}

// ---------------- normalize codebook rows -> fp16 hi (argmax pass needs only hi) ----------
__global__ __launch_bounds__(128) void k_norm_m(const float* __restrict__ m,
                                                __half* __restrict__ dh) {
    int k = blockIdx.x, tid = threadIdx.x;
    float4 v = ((const float4*)(m + (size_t)k * CDIM))[tid];
    float ss = v.x*v.x + v.y*v.y + v.z*v.z + v.w*v.w;
    #pragma unroll
    for (int o = 16; o; o >>= 1) ss += __shfl_xor_sync(~0u, ss, o);
    __shared__ float sred[4]; __shared__ float sinv;
    if ((tid & 31) == 0) sred[tid >> 5] = ss;
    __syncthreads();
    if (tid == 0) sinv = 1.f / fmaxf(sqrtf(sred[0]+sred[1]+sred[2]+sred[3]), 1e-12f);
    __syncthreads();
    float inv = sinv;
    float o4[4] = {v.x*inv, v.y*inv, v.z*inv, v.w*inv};
    size_t base = (size_t)k * CDIM + tid * 4;
    #pragma unroll
    for (int j = 0; j < 4; j++) dh[base + j] = __float2half_rn(o4[j]);
}

// ---------------- EMA update + normalize -> fp16 hi/lo ----------------
__global__ __launch_bounds__(128) void k_update_m(const float* __restrict__ m) {
    int k = blockIdx.x, tid = threadIdx.x;
    float w = 0.001f / (g_cnt[k] + 1e-6f);
    float4 mv = ((const float4*)(m      + (size_t)k * CDIM))[tid];
    float4 ev = ((const float4*)(g_esum + (size_t)k * CDIM))[tid];
    float nv[4] = { mv.x*0.999f + ev.x*w, mv.y*0.999f + ev.y*w,
                    mv.z*0.999f + ev.z*w, mv.w*0.999f + ev.w*w };
    float ss = nv[0]*nv[0] + nv[1]*nv[1] + nv[2]*nv[2] + nv[3]*nv[3];
    #pragma unroll
    for (int o = 16; o; o >>= 1) ss += __shfl_xor_sync(~0u, ss, o);
    __shared__ float sred[4]; __shared__ float sinv;
    if ((tid & 31) == 0) sred[tid >> 5] = ss;
    __syncthreads();
    if (tid == 0) sinv = 1.f / fmaxf(sqrtf(sred[0]+sred[1]+sred[2]+sred[3]), 1e-12f);
    __syncthreads();
    float inv = sinv;
    size_t base = (size_t)k * CDIM + tid * 4;
    #pragma unroll
    for (int j = 0; j < 4; j++) {
        float v = nv[j] * inv;
        __half h = __float2half_rn(v);
        g_m2h[base + j] = h;
        g_m2l[base + j] = __float2half_rn(v - __half2float(h));
    }
}

// ---------------- transpose std (K,V)->(V,K), fp16 hi/lo ----------------
__global__ void k_tstd(const float* __restrict__ s) {
    __shared__ float t[32][33];
    int v0 = blockIdx.x * 32, k0 = blockIdx.y * 32;
    int tx = threadIdx.x, ty = threadIdx.y;  // 32 x 8
    #pragma unroll
    for (int i = 0; i < 4; i++)
        t[ty + 8*i][tx] = s[(size_t)(k0 + ty + 8*i) * VC + v0 + tx];
    __syncthreads();
    #pragma unroll
    for (int i = 0; i < 4; i++) {
        float v = t[tx][ty + 8*i];
        __half h = __float2half_rn(v);
        size_t o = (size_t)(v0 + ty + 8*i) * KN + k0 + tx;
        g_sth[o] = h;
        g_stl[o] = __float2half_rn(v - __half2float(h));
    }
}

// ---------------- transpose (b,c,h,w)->(n,c), normalize rows -> fp16 hi only ----------------
__global__ __launch_bounds__(256) void k_prep_x(const float* __restrict__ x) {
    __shared__ float s[CDIM][17];
    __shared__ float rsum[16][17];
    int bid = blockIdx.x;             // 0..2047
    int b   = bid >> 8;               // / 256
    int hw0 = (bid & 255) << 4;       // * 16
    int tx = threadIdx.x & 15, ty = threadIdx.x >> 4;
    const float* xb = x + (size_t)b * CDIM * HW + hw0;
    float ss = 0.f;
    for (int c = ty; c < CDIM; c += 16) {
        float v = xb[(size_t)c * HW + tx];
        s[c][tx] = v;
        ss += v * v;
    }
    rsum[ty][tx] = ss;
    __syncthreads();
    if (ty < 8) rsum[ty][tx] += rsum[ty + 8][tx];
    __syncthreads();
    if (ty < 4) rsum[ty][tx] += rsum[ty + 4][tx];
    __syncthreads();
    if (ty < 2) rsum[ty][tx] += rsum[ty + 2][tx];
    __syncthreads();
    if (ty == 0) {
        float norm = fmaxf(sqrtf(rsum[0][tx] + rsum[1][tx]), 1e-12f);
        rsum[0][tx] = 1.f / norm;
    }
    __syncthreads();
    int warp = threadIdx.x >> 5, lane = threadIdx.x & 31;
    #pragma unroll
    for (int q = 0; q < 2; q++) {
        int p = warp * 2 + q;
        float inv = rsum[0][p];
        size_t rbase = (size_t)(b * HW + hw0 + p) * CDIM;
        for (int c = lane; c < CDIM; c += 32)
            g_xh[rbase + c] = __float2half_rn(s[c][p] * inv);
    }
}

// ---------------- zero segment buffers + argmax buffer ----------------
__global__ void k_zero() {
    int i = blockIdx.x * blockDim.x + threadIdx.x;
    if (i < KN * CDIM) g_esum[i] = 0.f;
    if (i < KN)        g_cnt[i]  = 0.f;
    if (i < NPIX)      g_arg[i]  = 0ull;
}

// ---------------- scatter: raw x -> esum via vectorized red; counts inline ----------------
// thread t: n = t & (NPIX-1), c quad = t >> 15 ; coalesced x reads (4 streams)
__global__ __launch_bounds__(256) void k_scatter(const float* __restrict__ x) {
    int t = blockIdx.x * blockDim.x + threadIdx.x;   // [0, NPIX*128)
    int n  = t & (NPIX - 1);
    int cq = t >> 15;            // 0..127
    int c0 = cq << 2;
    int idx = (int)(~(unsigned)(g_arg[n] & 0xFFFFFFFFull));
    int b = n >> 12, hw = n & (HW - 1);
    const float* xb = x + (size_t)b * CDIM * HW + (size_t)c0 * HW + hw;
    float v0 = xb[0];
    float v1 = xb[HW];
    float v2 = xb[2 * HW];
    float v3 = xb[3 * HW];
    float* dst = g_esum + (size_t)idx * CDIM + c0;
    asm volatile("red.global.add.v4.f32 [%0], {%1,%2,%3,%4};"
                 :: "l"(dst), "f"(v0), "f"(v1), "f"(v2), "f"(v3) : "memory");
    if (cq == 0) atomicAdd(&g_cnt[idx], 1.f);
}

// ---------------- softmax rows of score2 -> fp16 hi/lo prob ----------------
__global__ __launch_bounds__(256) void k_softmax(const float* __restrict__ s2) {
    int n = blockIdx.x, tid = threadIdx.x;
    float4 v = ((const float4*)(s2 + (size_t)n * KN))[tid];
    float mx = fmaxf(fmaxf(v.x, v.y), fmaxf(v.z, v.w));
    #pragma unroll
    for (int o = 16; o; o >>= 1) mx = fmaxf(mx, __shfl_xor_sync(~0u, mx, o));
    __shared__ float sm[8];
    if ((tid & 31) == 0) sm[tid >> 5] = mx;
    __syncthreads();
    if (tid < 32) {
        float t = (tid < 8) ? sm[tid] : -3.4e38f;
        #pragma unroll
        for (int o = 4; o; o >>= 1) t = fmaxf(t, __shfl_xor_sync(~0u, t, o));
        if (tid == 0) sm[0] = t;
    }
    __syncthreads();
    float M = sm[0];
    float e0 = __expf(v.x - M), e1 = __expf(v.y - M);
    float e2 = __expf(v.z - M), e3 = __expf(v.w - M);
    float ssum = e0 + e1 + e2 + e3;
    #pragma unroll
    for (int o = 16; o; o >>= 1) ssum += __shfl_xor_sync(~0u, ssum, o);
    __shared__ float sq[8];
    if ((tid & 31) == 0) sq[tid >> 5] = ssum;
    __syncthreads();
    if (tid < 32) {
        float t = (tid < 8) ? sq[tid] : 0.f;
        #pragma unroll
        for (int o = 4; o; o >>= 1) t += __shfl_xor_sync(~0u, t, o);
        if (tid == 0) sq[0] = t;
    }
    __syncthreads();
    float inv = 1.f / sq[0];
    float p[4] = {e0 * inv, e1 * inv, e2 * inv, e3 * inv};
    size_t base = (size_t)n * KN + tid * 4;
    #pragma unroll
    for (int j = 0; j < 4; j++) {
        __half h = __float2half_rn(p[j]);
        g_ph[base + j] = h;
        g_pl[base + j] = __float2half_rn(p[j] - __half2float(h));
    }
}

// ---------------- launch ----------------
extern "C" void kernel_launch(void* const* d_in, const int* in_sizes, int n_in,
                              void* d_out, int out_size) {
    const float* x    = (const float*)d_in[0];   // (8,512,64,64)
    const float* m    = (const float*)d_in[1];   // (1024,512)
    const float* stdw = (const float*)d_in[2];   // (1024,512)
    float* out = (float*)d_out;

    __half *p_xh, *p_mh, *p_m2h, *p_m2l, *p_sth, *p_stl, *p_ph, *p_pl;
    float* p_prob;
    cudaGetSymbolAddress((void**)&p_xh,  g_xh);
    cudaGetSymbolAddress((void**)&p_mh,  g_mh);
    cudaGetSymbolAddress((void**)&p_m2h, g_m2h);
    cudaGetSymbolAddress((void**)&p_m2l, g_m2l);
    cudaGetSymbolAddress((void**)&p_sth, g_sth);
    cudaGetSymbolAddress((void**)&p_stl, g_stl);
    cudaGetSymbolAddress((void**)&p_ph,  g_ph);
    cudaGetSymbolAddress((void**)&p_pl,  g_pl);
    cudaGetSymbolAddress((void**)&p_prob, g_prob);

    cudaFuncSetAttribute(k_mma, cudaFuncAttributeMaxDynamicSharedMemorySize, SMEM_DYN);

    const long long OUT1 = (long long)NPIX * VC;
    const long long S2SZ = (long long)NPIX * KN;
    float* s2 = ((long long)out_size >= OUT1 + S2SZ) ? (out + OUT1) : p_prob;

    k_norm_m <<<KN, 128>>>(m, p_mh);
    k_prep_x <<<2048, 256>>>(x);
    k_zero   <<<(KN * CDIM + 255) / 256, 256>>>();
    // GEMM1: score1 + argmax (1-pass fp16 hi); grid = (col tiles, row tiles)
    k_mma<<<dim3(KN / 256, NPIX / 128), 256, SMEM_DYN>>>(p_xh, p_mh, nullptr,
                                                         CDIM, KN, 0, nullptr);
    k_scatter<<<(NPIX * 128) / 256, 256>>>(x);
    k_update_m<<<KN, 128>>>(m);
    k_tstd   <<<dim3(VC / 32, KN / 32), dim3(32, 8)>>>(stdw);
    // GEMM2: score2 (2-pass: Ah*Bh + Ah*Bl)
    k_mma<<<dim3(KN / 256, NPIX / 128), 256, SMEM_DYN>>>(p_xh, p_m2h, p_m2l,
                                                         CDIM, KN, 1, s2);
    k_softmax<<<NPIX, 256>>>(s2);
    // GEMM3: out = prob @ std (2-pass, operands prob(N,K), std^T(V,K))
    k_mma<<<dim3(VC / 256, NPIX / 128), 256, SMEM_DYN>>>(p_ph, p_sth, p_stl,
                                                         KN, VC, 2, out);
}